// round 13
// baseline (speedup 1.0000x reference)
#include <cuda_runtime.h>
#include <cstdint>
#include <math.h>

#define EN_MAX 200000
#define TN_MAX 600000
#define HH 128
#define IC 64
#define BSZ 8
#define NRAD 6
#define SBFK 42
#define TK 294

typedef unsigned long long ull;

// ---------------- scratch (device globals; no allocations) ----------------
__device__ float g_xji[EN_MAX * HH];
__device__ float g_rbfh[EN_MAX * HH];
__device__ float g_rbfh2[EN_MAX * HH];
__device__ float g_rb8[EN_MAX * BSZ];
__device__ float g_xdown[EN_MAX * IC];
__device__ float g_acc[EN_MAX * IC];
__device__ float g_t8[TN_MAX * BSZ];
__device__ float g_s8[TN_MAX * BSZ];
__device__ float g_bufA[EN_MAX * HH];
__device__ float g_bufB[EN_MAX * HH];
__device__ float g_bufC[EN_MAX * HH];
// CSR index for segment_sum
__device__ int g_cnt[EN_MAX];
__device__ int g_offs[EN_MAX];
__device__ int g_cursor[EN_MAX];
__device__ int g_part[1024];
__device__ int g_perm[TN_MAX];

__device__ __forceinline__ float silu_f(float x) {
    return x / (1.0f + __expf(-x));
}

__device__ __forceinline__ void ffma2(ull& c, ull a, ull b) {
    asm("fma.rn.f32x2 %0, %1, %2, %0;" : "+l"(c) : "l"(a), "l"(b));
}
__device__ __forceinline__ void unpack2(ull v, float& lo, float& hi) {
    unsigned int a, b;
    asm("mov.b64 {%0, %1}, %2;" : "=r"(a), "=r"(b) : "l"(v));
    lo = __uint_as_float(a);
    hi = __uint_as_float(b);
}
__device__ __forceinline__ uint32_t smem_u32(const void* p) {
    uint32_t a;
    asm("{ .reg .u64 t; cvta.to.shared.u64 t, %1; cvt.u32.u64 %0, t; }" : "=r"(a) : "l"(p));
    return a;
}

// ---------------- FFMA2 GEMM (R7 config, unchanged: ~204us/stage) ---------
template <int KIN, int NOUT>
__global__ void __launch_bounds__(256, 2)
gemm_f2(const float* __restrict__ in,
        const float* __restrict__ W,
        const float* __restrict__ bias,
        const float* __restrict__ mulv,
        const float* __restrict__ addv,
        float* __restrict__ out,
        const float* __restrict__ mul2,
        float* __restrict__ out2,
        int nrows, int act)
{
    constexpr int KB = 64;
    constexpr int NC = KIN / KB;
    constexpr int APITCH = 132;
    constexpr int NQ = NOUT / 32;
    constexpr int NPAIR = NOUT / 2;

    extern __shared__ char smem[];
    float* As = reinterpret_cast<float*>(smem);
    ull*   Bs = reinterpret_cast<ull*>(smem + KB * APITCH * 4);

    const int tid = threadIdx.x;
    const int tr = tid >> 4;
    const int tc = tid & 15;
    const int r0 = blockIdx.x * 128;

    ull acc[4][NQ][2];
    #pragma unroll
    for (int p = 0; p < 4; ++p)
        #pragma unroll
        for (int q = 0; q < NQ; ++q) { acc[p][q][0] = 0ull; acc[p][q][1] = 0ull; }

    for (int c = 0; c < NC; ++c) {
        if (c) __syncthreads();
        {
            const int row = tid >> 1, part = tid & 1;
            int gr = r0 + row;
            if (gr >= nrows) gr = nrows - 1;
            const float* src = in + (size_t)gr * KIN + c * KB + part * 32;
            #pragma unroll
            for (int f = 0; f < 8; ++f) {
                const float4 v = *reinterpret_cast<const float4*>(src + f * 4);
                const int kk = part * 32 + f * 4;
                As[(kk + 0) * APITCH + row] = v.x;
                As[(kk + 1) * APITCH + row] = v.y;
                As[(kk + 2) * APITCH + row] = v.z;
                As[(kk + 3) * APITCH + row] = v.w;
            }
        }
        {
            #pragma unroll
            for (int t = tid; t < KB * NPAIR; t += 256) {
                const int k = t / NPAIR, P = t % NPAIR;
                const float2 w = *reinterpret_cast<const float2*>(
                    W + (size_t)(c * KB + k) * NOUT + 2 * P);
                const uint32_t bx = __float_as_uint(w.x), by = __float_as_uint(w.y);
                *reinterpret_cast<uint4*>(Bs + (size_t)k * NOUT + 2 * P) =
                    make_uint4(bx, bx, by, by);
            }
        }
        __syncthreads();

        #pragma unroll 8
        for (int k = 0; k < KB; ++k) {
            const ulonglong2* ap = reinterpret_cast<const ulonglong2*>(As + k * APITCH + tr * 8);
            const ulonglong2 a01 = ap[0], a23 = ap[1];
            const ull a[4] = {a01.x, a01.y, a23.x, a23.y};
            const ull* bk = Bs + (size_t)k * NOUT;
            #pragma unroll
            for (int q = 0; q < NQ; ++q) {
                const ulonglong2 b = *reinterpret_cast<const ulonglong2*>(bk + q * 32 + tc * 2);
                #pragma unroll
                for (int p = 0; p < 4; ++p) {
                    ffma2(acc[p][q][0], a[p], b.x);
                    ffma2(acc[p][q][1], a[p], b.y);
                }
            }
        }
    }

    float bv[NQ][2];
    #pragma unroll
    for (int q = 0; q < NQ; ++q) {
        const int col = 2 * tc + 32 * q;
        bv[q][0] = bias ? bias[col] : 0.f;
        bv[q][1] = bias ? bias[col + 1] : 0.f;
    }

    #pragma unroll
    for (int p = 0; p < 4; ++p) {
        float ve[NQ][2], vo[NQ][2];
        #pragma unroll
        for (int q = 0; q < NQ; ++q) {
            unpack2(acc[p][q][0], ve[q][0], vo[q][0]);
            unpack2(acc[p][q][1], ve[q][1], vo[q][1]);
        }
        #pragma unroll
        for (int half = 0; half < 2; ++half) {
            const int row = r0 + tr * 8 + 2 * p + half;
            if (row >= nrows) continue;
            #pragma unroll
            for (int q = 0; q < NQ; ++q) {
                const int col = 2 * tc + 32 * q;
                const size_t o = (size_t)row * NOUT + col;
                float v0 = (half ? vo : ve)[q][0] + bv[q][0];
                float v1 = (half ? vo : ve)[q][1] + bv[q][1];
                if (act) { v0 = silu_f(v0); v1 = silu_f(v1); }
                if (mulv) {
                    const float2 m = *reinterpret_cast<const float2*>(mulv + o);
                    v0 *= m.x; v1 *= m.y;
                }
                if (addv) {
                    const float2 s = *reinterpret_cast<const float2*>(addv + o);
                    v0 += s.x; v1 += s.y;
                }
                *reinterpret_cast<float2*>(out + o) = make_float2(v0, v1);
                if (out2) {
                    const float2 m = *reinterpret_cast<const float2*>(mul2 + o);
                    *reinterpret_cast<float2*>(out2 + o) = make_float2(v0 * m.x, v1 * m.y);
                }
            }
        }
    }
}

// ---------------- rbf basis helpers ----------------
__global__ void rb8_kernel(const float* __restrict__ rbf, const float* __restrict__ W1,
                           float* __restrict__ out, int n)
{
    const int e = blockIdx.x * blockDim.x + threadIdx.x;
    if (e >= n) return;
    float r[NRAD];
    #pragma unroll
    for (int i = 0; i < NRAD; ++i) r[i] = rbf[(size_t)e * NRAD + i];
    #pragma unroll
    for (int b = 0; b < BSZ; ++b) {
        float s = 0.f;
        #pragma unroll
        for (int i = 0; i < NRAD; ++i) s += r[i] * __ldg(&W1[i * BSZ + b]);
        out[(size_t)e * BSZ + b] = s;
    }
}

__global__ void rbfh_kernel(const float* __restrict__ rb8, const float* __restrict__ rbf,
                            const float* __restrict__ W_rbf2, const float* __restrict__ W_rbf,
                            float* __restrict__ rbfh, float* __restrict__ rbfh2, int n)
{
    __shared__ float w2[BSZ * HH];
    __shared__ float wr[NRAD * HH];
    const int j = threadIdx.x;
    #pragma unroll
    for (int b = 0; b < BSZ; ++b) w2[b * HH + j] = W_rbf2[b * HH + j];
    #pragma unroll
    for (int r = 0; r < NRAD; ++r) wr[r * HH + j] = W_rbf[r * HH + j];
    __syncthreads();

    const int row0 = blockIdx.x * 32;
    for (int rr = 0; rr < 32; ++rr) {
        const int row = row0 + rr;
        if (row >= n) return;
        const float4* rp = reinterpret_cast<const float4*>(rb8 + (size_t)row * BSZ);
        const float4 ra = __ldg(rp), rb = __ldg(rp + 1);
        float a1 = ra.x * w2[0 * HH + j] + ra.y * w2[1 * HH + j] +
                   ra.z * w2[2 * HH + j] + ra.w * w2[3 * HH + j] +
                   rb.x * w2[4 * HH + j] + rb.y * w2[5 * HH + j] +
                   rb.z * w2[6 * HH + j] + rb.w * w2[7 * HH + j];
        float a2 = 0.f;
        #pragma unroll
        for (int r = 0; r < NRAD; ++r) a2 += __ldg(&rbf[(size_t)row * NRAD + r]) * wr[r * HH + j];
        rbfh[(size_t)row * HH + j]  = a1;
        rbfh2[(size_t)row * HH + j] = a2;
    }
}

// ------- T-space proj: cp.async double-buffered tile streamer (R9) --------
template <int K, int PK>
__global__ void __launch_bounds__(256)
proj8cp(const float* __restrict__ X, const float* __restrict__ W1,
        float* __restrict__ out8, int nrows)
{
    constexpr int ROWS = 24;
    constexpr int TILE_F = ROWS * K;
    constexpr int CH = (TILE_F * 4) / 16;
    constexpr int ITERS = (K + 31) / 32;

    extern __shared__ float sm[];
    float* wcm  = sm;
    float* red  = sm + 8 * PK;
    float* buf0 = red + 8 * 32 * 33;
    float* buf1 = buf0 + TILE_F;

    const int tid = threadIdx.x;
    for (int x = tid; x < 8 * PK; x += 256) wcm[x] = 0.f;
    __syncthreads();
    for (int x = tid; x < K * 8; x += 256) {
        const int i = x / 8, b = x % 8;
        wcm[b * PK + i] = W1[x];
    }

    const int warp = tid >> 5, lane = tid & 31;
    const int G = gridDim.x;
    const int ntiles = (nrows + ROWS - 1) / ROWS;
    float* myred = red + warp * (32 * 33);

    const uint32_t b0u = smem_u32(buf0), b1u = smem_u32(buf1);

    int it = 0;
    if ((int)blockIdx.x < ntiles) {
        const char* gsrc = (const char*)X + (size_t)blockIdx.x * (ROWS * K * 4);
        for (int c = tid; c < CH; c += 256)
            asm volatile("cp.async.cg.shared.global [%0], [%1], 16;"
                         :: "r"(b0u + c * 16), "l"(gsrc + (size_t)c * 16));
    }
    asm volatile("cp.async.commit_group;" ::: "memory");

    for (int tt = blockIdx.x; tt < ntiles; tt += G, ++it) {
        float* cur = (it & 1) ? buf1 : buf0;
        const uint32_t nxtu = (it & 1) ? b0u : b1u;
        const int tnext = tt + G;
        if (tnext < ntiles) {
            const char* gsrc = (const char*)X + (size_t)tnext * (ROWS * K * 4);
            for (int c = tid; c < CH; c += 256)
                asm volatile("cp.async.cg.shared.global [%0], [%1], 16;"
                             :: "r"(nxtu + c * 16), "l"(gsrc + (size_t)c * 16));
            asm volatile("cp.async.commit_group;" ::: "memory");
            asm volatile("cp.async.wait_group 1;" ::: "memory");
        } else {
            asm volatile("cp.async.commit_group;" ::: "memory");
            asm volatile("cp.async.wait_group 0;" ::: "memory");
        }
        __syncthreads();

        const int r0 = tt * ROWS;
        float acc[3][BSZ] = {};
        const float* xb = cur + (3 * warp) * K;
        #pragma unroll
        for (int k = 0; k < ITERS; ++k) {
            const int ii = lane + k * 32;
            float x0 = 0.f, x1 = 0.f, x2 = 0.f;
            if (ii < K) { x0 = xb[ii]; x1 = xb[K + ii]; x2 = xb[2 * K + ii]; }
            #pragma unroll
            for (int b = 0; b < BSZ; ++b) {
                const float w = wcm[b * PK + ii];
                acc[0][b] += w * x0; acc[1][b] += w * x1; acc[2][b] += w * x2;
            }
        }
        #pragma unroll
        for (int rr = 0; rr < 3; ++rr)
            #pragma unroll
            for (int b = 0; b < BSZ; ++b)
                myred[lane * 33 + rr * BSZ + b] = acc[rr][b];
        __syncwarp();
        if (lane < 24) {
            float s = 0.f;
            #pragma unroll
            for (int l = 0; l < 32; ++l) s += myred[l * 33 + lane];
            const int row = r0 + 3 * warp + (lane >> 3);
            if (row < nrows)
                out8[(size_t)(r0 + 3 * warp) * BSZ + lane] = s;
        }
        __syncthreads();
    }
}

// ---------------- CSR build: histogram, 2-level scan, permute -------------
__global__ void zcnt_kernel(int* __restrict__ cnt, int n)
{
    const int i = blockIdx.x * blockDim.x + threadIdx.x;
    if (i < n) cnt[i] = 0;
}

__global__ void hist_kernel(const int* __restrict__ idx_ji, int* __restrict__ cnt, int nt)
{
    const int t = blockIdx.x * blockDim.x + threadIdx.x;
    if (t < nt) atomicAdd(cnt + idx_ji[t], 1);
}

__global__ void scan1_kernel(const int* __restrict__ cnt, int* __restrict__ offs,
                             int* __restrict__ part, int n)
{
    __shared__ int s[256];
    const int i = blockIdx.x * 256 + threadIdx.x;
    const int v = (i < n) ? cnt[i] : 0;
    s[threadIdx.x] = v;
    __syncthreads();
    #pragma unroll
    for (int d = 1; d < 256; d <<= 1) {
        const int t = (threadIdx.x >= d) ? s[threadIdx.x - d] : 0;
        __syncthreads();
        s[threadIdx.x] += t;
        __syncthreads();
    }
    if (i < n) offs[i] = s[threadIdx.x] - v;   // exclusive
    if (threadIdx.x == 255) part[blockIdx.x] = s[255];
}

__global__ void scan2_kernel(int* __restrict__ part, int nb)
{
    __shared__ int s[1024];
    const int v = (threadIdx.x < nb) ? part[threadIdx.x] : 0;
    s[threadIdx.x] = v;
    __syncthreads();
    #pragma unroll
    for (int d = 1; d < 1024; d <<= 1) {
        const int t = (threadIdx.x >= d) ? s[threadIdx.x - d] : 0;
        __syncthreads();
        s[threadIdx.x] += t;
        __syncthreads();
    }
    if (threadIdx.x < nb) part[threadIdx.x] = s[threadIdx.x] - v;   // exclusive
}

__global__ void scan3_kernel(int* __restrict__ offs, int* __restrict__ cursor,
                             const int* __restrict__ part, int n)
{
    const int i = blockIdx.x * 256 + threadIdx.x;
    if (i < n) {
        const int o = offs[i] + part[blockIdx.x];
        offs[i] = o;
        cursor[i] = o;
    }
}

__global__ void permute_kernel(const int* __restrict__ idx_ji, int* __restrict__ cursor,
                               int* __restrict__ perm, int nt)
{
    const int t = blockIdx.x * blockDim.x + threadIdx.x;
    if (t < nt) {
        const int pos = atomicAdd(cursor + idx_ji[t], 1);
        perm[pos] = t;
    }
}

// -------- CSR accumulate: warp per edge, gather + register sum, 1 store ---
__global__ void __launch_bounds__(256)
tacc_kernel(const float* __restrict__ t8, const float* __restrict__ s8,
            const float* __restrict__ W_t2, const float* __restrict__ W_sbf2,
            const float* __restrict__ xdown,
            const int* __restrict__ idx_kj,
            const int* __restrict__ cnt, const int* __restrict__ offs,
            const int* __restrict__ perm,
            float* __restrict__ acc, int ne)
{
    __shared__ float2 wt2s[BSZ * 32];
    __shared__ float2 ws2s[BSZ * 32];
    const int tid = threadIdx.x;
    for (int i = tid; i < BSZ * 32; i += blockDim.x) {
        wt2s[i] = reinterpret_cast<const float2*>(W_t2)[i];
        ws2s[i] = reinterpret_cast<const float2*>(W_sbf2)[i];
    }
    __syncthreads();

    const int warp = tid >> 5, lane = tid & 31;
    const int e = blockIdx.x * 8 + warp;
    if (e >= ne) return;

    const int n = cnt[e], off = offs[e];
    float ax = 0.f, ay = 0.f;
    for (int i = 0; i < n; ++i) {
        const int t = __ldg(perm + off + i);
        const int kj = __ldg(idx_kj + t);
        const float4* tp = reinterpret_cast<const float4*>(t8 + (size_t)t * BSZ);
        const float4 ta = __ldg(tp), tb = __ldg(tp + 1);
        const float4* sp = reinterpret_cast<const float4*>(s8 + (size_t)t * BSZ);
        const float4 sa = __ldg(sp), sb = __ldg(sp + 1);
        const float2 g = __ldg(reinterpret_cast<const float2*>(xdown + (size_t)kj * IC) + lane);
        const float tv[BSZ] = {ta.x, ta.y, ta.z, ta.w, tb.x, tb.y, tb.z, tb.w};
        const float sv[BSZ] = {sa.x, sa.y, sa.z, sa.w, sb.x, sb.y, sb.z, sb.w};
        float t0 = 0.f, t1 = 0.f, s0 = 0.f, s1 = 0.f;
        #pragma unroll
        for (int b = 0; b < BSZ; ++b) {
            const float2 wt = wt2s[b * 32 + lane];
            const float2 ws = ws2s[b * 32 + lane];
            t0 += tv[b] * wt.x; t1 += tv[b] * wt.y;
            s0 += sv[b] * ws.x; s1 += sv[b] * ws.y;
        }
        ax += g.x * t0 * s0;
        ay += g.y * t1 * s1;
    }
    reinterpret_cast<float2*>(acc + (size_t)e * IC)[lane] = make_float2(ax, ay);
}

// ---------------- launch (serial; idx 3 = rbfh profiled) ------------------
extern "C" void kernel_launch(void* const* d_in, const int* in_sizes, int n_in,
                              void* d_out, int out_size)
{
    const float* e1     = (const float*)d_in[0];
    const float* rbf    = (const float*)d_in[1];
    const float* sbf    = (const float*)d_in[2];
    const float* tt     = (const float*)d_in[3];
    const int*   idx_kj = (const int*)d_in[4];
    const int*   idx_ji = (const int*)d_in[5];
    const float* W_rbf1 = (const float*)d_in[6];
    const float* W_rbf2 = (const float*)d_in[7];
    const float* W_sbf1 = (const float*)d_in[8];
    const float* W_sbf2 = (const float*)d_in[9];
    const float* W_t1   = (const float*)d_in[10];
    const float* W_t2   = (const float*)d_in[11];
    const float* W_rbf  = (const float*)d_in[12];
    const float* W_kj   = (const float*)d_in[13];
    const float* b_kj   = (const float*)d_in[14];
    const float* W_ji   = (const float*)d_in[15];
    const float* b_ji   = (const float*)d_in[16];
    const float* W_down = (const float*)d_in[17];
    const float* W_up   = (const float*)d_in[18];
    const float* Wb1    = (const float*)d_in[19];
    const float* bb1    = (const float*)d_in[20];
    const float* Wb2    = (const float*)d_in[21];
    const float* bb2    = (const float*)d_in[22];
    const float* W_lin  = (const float*)d_in[23];
    const float* b_lin  = (const float*)d_in[24];
    const float* Wa1    = (const float*)d_in[25];
    const float* ba1    = (const float*)d_in[26];
    const float* Wa2    = (const float*)d_in[27];
    const float* ba2    = (const float*)d_in[28];

    const int E = in_sizes[0] / HH;
    const int T = in_sizes[4];

    float *xji, *rbfh, *rbfh2, *rb8, *xdown, *acc, *t8, *s8, *A, *B, *C;
    int *cnt, *offs, *cursor, *part, *perm;
    cudaGetSymbolAddress((void**)&xji,    g_xji);
    cudaGetSymbolAddress((void**)&rbfh,   g_rbfh);
    cudaGetSymbolAddress((void**)&rbfh2,  g_rbfh2);
    cudaGetSymbolAddress((void**)&rb8,    g_rb8);
    cudaGetSymbolAddress((void**)&xdown,  g_xdown);
    cudaGetSymbolAddress((void**)&acc,    g_acc);
    cudaGetSymbolAddress((void**)&t8,     g_t8);
    cudaGetSymbolAddress((void**)&s8,     g_s8);
    cudaGetSymbolAddress((void**)&A,      g_bufA);
    cudaGetSymbolAddress((void**)&B,      g_bufB);
    cudaGetSymbolAddress((void**)&C,      g_bufC);
    cudaGetSymbolAddress((void**)&cnt,    g_cnt);
    cudaGetSymbolAddress((void**)&offs,   g_offs);
    cudaGetSymbolAddress((void**)&cursor, g_cursor);
    cudaGetSymbolAddress((void**)&part,   g_part);
    cudaGetSymbolAddress((void**)&perm,   g_perm);

    float* out_e1 = (float*)d_out;
    float* out_e2 = (float*)d_out + (size_t)E * HH;

    const int WS = HH * HH;

    const int sm_hh = 64 * 132 * 4 + 64 * 128 * 8;   // 99328
    const int sm_dn = 64 * 132 * 4 + 64 * 64 * 8;    // 66560
    const int sm_up = 64 * 132 * 4 + 64 * 128 * 8;   // 99328
    cudaFuncSetAttribute(gemm_f2<HH, HH>, cudaFuncAttributeMaxDynamicSharedMemorySize, sm_hh);
    cudaFuncSetAttribute(gemm_f2<HH, IC>, cudaFuncAttributeMaxDynamicSharedMemorySize, sm_dn);
    cudaFuncSetAttribute(gemm_f2<IC, HH>, cudaFuncAttributeMaxDynamicSharedMemorySize, sm_up);

    const int sm_pt = (8 * 320 + 8 * 32 * 33 + 2 * 24 * TK) * 4;    // 100480
    const int sm_ps = (8 * 64 + 8 * 32 * 33 + 2 * 24 * SBFK) * 4;   // 43904
    cudaFuncSetAttribute(proj8cp<TK, 320>, cudaFuncAttributeMaxDynamicSharedMemorySize, sm_pt);
    cudaFuncSetAttribute(proj8cp<SBFK, 64>, cudaFuncAttributeMaxDynamicSharedMemorySize, sm_ps);

    const int gblocks = (E + 127) / 128;
    const int SB = (E + 255) / 256;      // scan blocks (782 for E=200K)

    // serial; launch idx 3 (4th) = rbfh_kernel -> profiled
    proj8cp<TK, 320><<<296, 256, sm_pt>>>(tt, W_t1, t8, T);                          // 0
    proj8cp<SBFK, 64><<<296, 256, sm_ps>>>(sbf, W_sbf1, s8, T);                      // 1
    rb8_kernel<<<(E + 255) / 256, 256>>>(rbf, W_rbf1, rb8, E);                       // 2
    rbfh_kernel<<<(E + 31) / 32, HH>>>(rb8, rbf, W_rbf2, W_rbf, rbfh, rbfh2, E);     // 3 (profiled)
    // CSR build
    zcnt_kernel<<<SB, 256>>>(cnt, E);                                                // 4
    hist_kernel<<<(T + 255) / 256, 256>>>(idx_ji, cnt, T);                           // 5
    scan1_kernel<<<SB, 256>>>(cnt, offs, part, E);                                   // 6
    scan2_kernel<<<1, 1024>>>(part, SB);                                             // 7
    scan3_kernel<<<SB, 256>>>(offs, cursor, part, E);                                // 8
    permute_kernel<<<(T + 255) / 256, 256>>>(idx_ji, cursor, perm, T);               // 9
    // message gemms
    gemm_f2<HH, HH><<<gblocks, 256, sm_hh>>>(e1, W_kj, b_kj, rbfh, nullptr, A, nullptr, nullptr, E, 1);
    gemm_f2<HH, IC><<<gblocks, 256, sm_dn>>>(A, W_down, nullptr, nullptr, nullptr, xdown, nullptr, nullptr, E, 1);
    gemm_f2<HH, HH><<<gblocks, 256, sm_hh>>>(e1, W_ji, b_ji, nullptr, nullptr, xji, nullptr, nullptr, E, 1);
    // CSR segment-sum accumulate (no atomics)
    tacc_kernel<<<(E + 7) / 8, 256>>>(t8, s8, W_t2, W_sbf2, xdown, idx_kj,
                                      cnt, offs, perm, acc, E);
    // A = silu(acc @ W_up) + x_ji
    gemm_f2<IC, HH><<<gblocks, 256, sm_up>>>(acc, W_up, nullptr, nullptr, xji, A, nullptr, nullptr, E, 1);
    // residual before (1 layer)
    gemm_f2<HH, HH><<<gblocks, 256, sm_hh>>>(A, Wb1, bb1, nullptr, nullptr, B, nullptr, nullptr, E, 1);
    gemm_f2<HH, HH><<<gblocks, 256, sm_hh>>>(B, Wb2, bb2, nullptr, A, C, nullptr, nullptr, E, 1);
    // h = silu(C @ W_lin + b_lin) + e1
    gemm_f2<HH, HH><<<gblocks, 256, sm_hh>>>(C, W_lin, b_lin, nullptr, e1, A, nullptr, nullptr, E, 1);
    // residual after layer 0
    gemm_f2<HH, HH><<<gblocks, 256, sm_hh>>>(A, Wa1, ba1, nullptr, nullptr, B, nullptr, nullptr, E, 1);
    gemm_f2<HH, HH><<<gblocks, 256, sm_hh>>>(B, Wa2, ba2, nullptr, A, C, nullptr, nullptr, E, 1);
    // residual after layer 1 -> final outputs
    gemm_f2<HH, HH><<<gblocks, 256, sm_hh>>>(C, Wa1 + WS, ba1 + HH, nullptr, nullptr, B, nullptr, nullptr, E, 1);
    gemm_f2<HH, HH><<<gblocks, 256, sm_hh>>>(B, Wa2 + WS, ba2 + HH, nullptr, C, out_e1, rbfh2, out_e2, E, 1);
}

// round 14
// speedup vs baseline: 1.0310x; 1.0310x over previous
#include <cuda_runtime.h>
#include <cstdint>
#include <math.h>

#define EN_MAX 200000
#define TN_MAX 600000
#define HH 128
#define IC 64
#define BSZ 8
#define NRAD 6
#define SBFK 42
#define TK 294

typedef unsigned long long ull;

// ---------------- scratch (device globals; no allocations) ----------------
__device__ float g_xji[EN_MAX * HH];
__device__ float g_rbfh[EN_MAX * HH];
__device__ float g_rbfh2[EN_MAX * HH];
__device__ float g_rb8[EN_MAX * BSZ];
__device__ float g_xdown[EN_MAX * IC];
__device__ float g_acc[EN_MAX * IC];
__device__ float g_t8[TN_MAX * BSZ];
__device__ float g_s8[TN_MAX * BSZ];
__device__ float g_bufA[EN_MAX * HH];
__device__ float g_bufB[EN_MAX * HH];
__device__ float g_bufC[EN_MAX * HH];

__device__ __forceinline__ float silu_f(float x) {
    return x / (1.0f + __expf(-x));
}

__device__ __forceinline__ void ffma2(ull& c, ull a, ull b) {
    asm("fma.rn.f32x2 %0, %1, %2, %0;" : "+l"(c) : "l"(a), "l"(b));
}
__device__ __forceinline__ void unpack2(ull v, float& lo, float& hi) {
    unsigned int a, b;
    asm("mov.b64 {%0, %1}, %2;" : "=r"(a), "=r"(b) : "l"(v));
    lo = __uint_as_float(a);
    hi = __uint_as_float(b);
}
__device__ __forceinline__ uint32_t smem_u32(const void* p) {
    uint32_t a;
    asm("{ .reg .u64 t; cvta.to.shared.u64 t, %1; cvt.u32.u64 %0, t; }" : "=r"(a) : "l"(p));
    return a;
}

// ---------------- FFMA2 GEMM (R7 config, unchanged) -----------------------
template <int KIN, int NOUT>
__global__ void __launch_bounds__(256, 2)
gemm_f2(const float* __restrict__ in,
        const float* __restrict__ W,
        const float* __restrict__ bias,
        const float* __restrict__ mulv,
        const float* __restrict__ addv,
        float* __restrict__ out,
        const float* __restrict__ mul2,
        float* __restrict__ out2,
        int nrows, int act)
{
    constexpr int KB = 64;
    constexpr int NC = KIN / KB;
    constexpr int APITCH = 132;
    constexpr int NQ = NOUT / 32;
    constexpr int NPAIR = NOUT / 2;

    extern __shared__ char smem[];
    float* As = reinterpret_cast<float*>(smem);
    ull*   Bs = reinterpret_cast<ull*>(smem + KB * APITCH * 4);

    const int tid = threadIdx.x;
    const int tr = tid >> 4;
    const int tc = tid & 15;
    const int r0 = blockIdx.x * 128;

    ull acc[4][NQ][2];
    #pragma unroll
    for (int p = 0; p < 4; ++p)
        #pragma unroll
        for (int q = 0; q < NQ; ++q) { acc[p][q][0] = 0ull; acc[p][q][1] = 0ull; }

    for (int c = 0; c < NC; ++c) {
        if (c) __syncthreads();
        {
            const int row = tid >> 1, part = tid & 1;
            int gr = r0 + row;
            if (gr >= nrows) gr = nrows - 1;
            const float* src = in + (size_t)gr * KIN + c * KB + part * 32;
            #pragma unroll
            for (int f = 0; f < 8; ++f) {
                const float4 v = *reinterpret_cast<const float4*>(src + f * 4);
                const int kk = part * 32 + f * 4;
                As[(kk + 0) * APITCH + row] = v.x;
                As[(kk + 1) * APITCH + row] = v.y;
                As[(kk + 2) * APITCH + row] = v.z;
                As[(kk + 3) * APITCH + row] = v.w;
            }
        }
        {
            #pragma unroll
            for (int t = tid; t < KB * NPAIR; t += 256) {
                const int k = t / NPAIR, P = t % NPAIR;
                const float2 w = *reinterpret_cast<const float2*>(
                    W + (size_t)(c * KB + k) * NOUT + 2 * P);
                const uint32_t bx = __float_as_uint(w.x), by = __float_as_uint(w.y);
                *reinterpret_cast<uint4*>(Bs + (size_t)k * NOUT + 2 * P) =
                    make_uint4(bx, bx, by, by);
            }
        }
        __syncthreads();

        #pragma unroll 8
        for (int k = 0; k < KB; ++k) {
            const ulonglong2* ap = reinterpret_cast<const ulonglong2*>(As + k * APITCH + tr * 8);
            const ulonglong2 a01 = ap[0], a23 = ap[1];
            const ull a[4] = {a01.x, a01.y, a23.x, a23.y};
            const ull* bk = Bs + (size_t)k * NOUT;
            #pragma unroll
            for (int q = 0; q < NQ; ++q) {
                const ulonglong2 b = *reinterpret_cast<const ulonglong2*>(bk + q * 32 + tc * 2);
                #pragma unroll
                for (int p = 0; p < 4; ++p) {
                    ffma2(acc[p][q][0], a[p], b.x);
                    ffma2(acc[p][q][1], a[p], b.y);
                }
            }
        }
    }

    float bv[NQ][2];
    #pragma unroll
    for (int q = 0; q < NQ; ++q) {
        const int col = 2 * tc + 32 * q;
        bv[q][0] = bias ? bias[col] : 0.f;
        bv[q][1] = bias ? bias[col + 1] : 0.f;
    }

    #pragma unroll
    for (int p = 0; p < 4; ++p) {
        float ve[NQ][2], vo[NQ][2];
        #pragma unroll
        for (int q = 0; q < NQ; ++q) {
            unpack2(acc[p][q][0], ve[q][0], vo[q][0]);
            unpack2(acc[p][q][1], ve[q][1], vo[q][1]);
        }
        #pragma unroll
        for (int half = 0; half < 2; ++half) {
            const int row = r0 + tr * 8 + 2 * p + half;
            if (row >= nrows) continue;
            #pragma unroll
            for (int q = 0; q < NQ; ++q) {
                const int col = 2 * tc + 32 * q;
                const size_t o = (size_t)row * NOUT + col;
                float v0 = (half ? vo : ve)[q][0] + bv[q][0];
                float v1 = (half ? vo : ve)[q][1] + bv[q][1];
                if (act) { v0 = silu_f(v0); v1 = silu_f(v1); }
                if (mulv) {
                    const float2 m = *reinterpret_cast<const float2*>(mulv + o);
                    v0 *= m.x; v1 *= m.y;
                }
                if (addv) {
                    const float2 s = *reinterpret_cast<const float2*>(addv + o);
                    v0 += s.x; v1 += s.y;
                }
                *reinterpret_cast<float2*>(out + o) = make_float2(v0, v1);
                if (out2) {
                    const float2 m = *reinterpret_cast<const float2*>(mul2 + o);
                    *reinterpret_cast<float2*>(out2 + o) = make_float2(v0 * m.x, v1 * m.y);
                }
            }
        }
    }
}

// ---------------- rbf basis helpers ----------------
__global__ void rb8_kernel(const float* __restrict__ rbf, const float* __restrict__ W1,
                           float* __restrict__ out, int n)
{
    const int e = blockIdx.x * blockDim.x + threadIdx.x;
    if (e >= n) return;
    float r[NRAD];
    #pragma unroll
    for (int i = 0; i < NRAD; ++i) r[i] = rbf[(size_t)e * NRAD + i];
    #pragma unroll
    for (int b = 0; b < BSZ; ++b) {
        float s = 0.f;
        #pragma unroll
        for (int i = 0; i < NRAD; ++i) s += r[i] * __ldg(&W1[i * BSZ + b]);
        out[(size_t)e * BSZ + b] = s;
    }
}

__global__ void rbfh_kernel(const float* __restrict__ rb8, const float* __restrict__ rbf,
                            const float* __restrict__ W_rbf2, const float* __restrict__ W_rbf,
                            float* __restrict__ rbfh, float* __restrict__ rbfh2, int n)
{
    __shared__ float w2[BSZ * HH];
    __shared__ float wr[NRAD * HH];
    const int j = threadIdx.x;
    #pragma unroll
    for (int b = 0; b < BSZ; ++b) w2[b * HH + j] = W_rbf2[b * HH + j];
    #pragma unroll
    for (int r = 0; r < NRAD; ++r) wr[r * HH + j] = W_rbf[r * HH + j];
    __syncthreads();

    const int row0 = blockIdx.x * 32;
    for (int rr = 0; rr < 32; ++rr) {
        const int row = row0 + rr;
        if (row >= n) return;
        const float4* rp = reinterpret_cast<const float4*>(rb8 + (size_t)row * BSZ);
        const float4 ra = __ldg(rp), rb = __ldg(rp + 1);
        float a1 = ra.x * w2[0 * HH + j] + ra.y * w2[1 * HH + j] +
                   ra.z * w2[2 * HH + j] + ra.w * w2[3 * HH + j] +
                   rb.x * w2[4 * HH + j] + rb.y * w2[5 * HH + j] +
                   rb.z * w2[6 * HH + j] + rb.w * w2[7 * HH + j];
        float a2 = 0.f;
        #pragma unroll
        for (int r = 0; r < NRAD; ++r) a2 += __ldg(&rbf[(size_t)row * NRAD + r]) * wr[r * HH + j];
        rbfh[(size_t)row * HH + j]  = a1;
        rbfh2[(size_t)row * HH + j] = a2;
    }
}

// ------- T-space proj: cp.async double-buffered tile streamer (R9) --------
template <int K, int PK>
__global__ void __launch_bounds__(256)
proj8cp(const float* __restrict__ X, const float* __restrict__ W1,
        float* __restrict__ out8, int nrows)
{
    constexpr int ROWS = 24;
    constexpr int TILE_F = ROWS * K;
    constexpr int CH = (TILE_F * 4) / 16;
    constexpr int ITERS = (K + 31) / 32;

    extern __shared__ float sm[];
    float* wcm  = sm;
    float* red  = sm + 8 * PK;
    float* buf0 = red + 8 * 32 * 33;
    float* buf1 = buf0 + TILE_F;

    const int tid = threadIdx.x;
    for (int x = tid; x < 8 * PK; x += 256) wcm[x] = 0.f;
    __syncthreads();
    for (int x = tid; x < K * 8; x += 256) {
        const int i = x / 8, b = x % 8;
        wcm[b * PK + i] = W1[x];
    }

    const int warp = tid >> 5, lane = tid & 31;
    const int G = gridDim.x;
    const int ntiles = (nrows + ROWS - 1) / ROWS;
    float* myred = red + warp * (32 * 33);

    const uint32_t b0u = smem_u32(buf0), b1u = smem_u32(buf1);

    int it = 0;
    if ((int)blockIdx.x < ntiles) {
        const char* gsrc = (const char*)X + (size_t)blockIdx.x * (ROWS * K * 4);
        for (int c = tid; c < CH; c += 256)
            asm volatile("cp.async.cg.shared.global [%0], [%1], 16;"
                         :: "r"(b0u + c * 16), "l"(gsrc + (size_t)c * 16));
    }
    asm volatile("cp.async.commit_group;" ::: "memory");

    for (int tt = blockIdx.x; tt < ntiles; tt += G, ++it) {
        float* cur = (it & 1) ? buf1 : buf0;
        const uint32_t nxtu = (it & 1) ? b0u : b1u;
        const int tnext = tt + G;
        if (tnext < ntiles) {
            const char* gsrc = (const char*)X + (size_t)tnext * (ROWS * K * 4);
            for (int c = tid; c < CH; c += 256)
                asm volatile("cp.async.cg.shared.global [%0], [%1], 16;"
                             :: "r"(nxtu + c * 16), "l"(gsrc + (size_t)c * 16));
            asm volatile("cp.async.commit_group;" ::: "memory");
            asm volatile("cp.async.wait_group 1;" ::: "memory");
        } else {
            asm volatile("cp.async.commit_group;" ::: "memory");
            asm volatile("cp.async.wait_group 0;" ::: "memory");
        }
        __syncthreads();

        const int r0 = tt * ROWS;
        float acc[3][BSZ] = {};
        const float* xb = cur + (3 * warp) * K;
        #pragma unroll
        for (int k = 0; k < ITERS; ++k) {
            const int ii = lane + k * 32;
            float x0 = 0.f, x1 = 0.f, x2 = 0.f;
            if (ii < K) { x0 = xb[ii]; x1 = xb[K + ii]; x2 = xb[2 * K + ii]; }
            #pragma unroll
            for (int b = 0; b < BSZ; ++b) {
                const float w = wcm[b * PK + ii];
                acc[0][b] += w * x0; acc[1][b] += w * x1; acc[2][b] += w * x2;
            }
        }
        #pragma unroll
        for (int rr = 0; rr < 3; ++rr)
            #pragma unroll
            for (int b = 0; b < BSZ; ++b)
                myred[lane * 33 + rr * BSZ + b] = acc[rr][b];
        __syncwarp();
        if (lane < 24) {
            float s = 0.f;
            #pragma unroll
            for (int l = 0; l < 32; ++l) s += myred[l * 33 + lane];
            const int row = r0 + 3 * warp + (lane >> 3);
            if (row < nrows)
                out8[(size_t)(r0 + 3 * warp) * BSZ + lane] = s;
        }
        __syncthreads();
    }
}

// ------- triplet gather/scale/scatter (EXACT R2/R3-era version) -----------
__global__ void triplet_kernel(const float* __restrict__ t8, const float* __restrict__ s8,
                               const float* __restrict__ W_t2, const float* __restrict__ W_sbf2,
                               const float* __restrict__ xdown,
                               const int* __restrict__ idx_kj, const int* __restrict__ idx_ji,
                               float* __restrict__ acc, int nt)
{
    __shared__ float wt2s[BSZ * IC];
    __shared__ float ws2s[BSZ * IC];
    const int tid = threadIdx.x;
    for (int i = tid; i < BSZ * IC; i += blockDim.x) { wt2s[i] = W_t2[i]; ws2s[i] = W_sbf2[i]; }
    __syncthreads();

    const int warp = tid >> 5, lane = tid & 31;
    const int total_warps = (blockDim.x * gridDim.x) >> 5;

    for (int tr = blockIdx.x * (blockDim.x >> 5) + warp; tr < nt; tr += total_warps) {
        const float4* tp = reinterpret_cast<const float4*>(t8 + (size_t)tr * BSZ);
        const float4 ta = __ldg(tp), tb = __ldg(tp + 1);
        const float4* sp = reinterpret_cast<const float4*>(s8 + (size_t)tr * BSZ);
        const float4 sa = __ldg(sp), sb = __ldg(sp + 1);
        const float tv[BSZ] = {ta.x, ta.y, ta.z, ta.w, tb.x, tb.y, tb.z, tb.w};
        const float sv[BSZ] = {sa.x, sa.y, sa.z, sa.w, sb.x, sb.y, sb.z, sb.w};
        const int kj = idx_kj[tr], ji = idx_ji[tr];
        const int c0 = lane, c1 = lane + 32;
        float t0 = 0.f, t1 = 0.f, s0 = 0.f, s1 = 0.f;
        #pragma unroll
        for (int b = 0; b < BSZ; ++b) {
            t0 += tv[b] * wt2s[b * IC + c0];
            t1 += tv[b] * wt2s[b * IC + c1];
            s0 += sv[b] * ws2s[b * IC + c0];
            s1 += sv[b] * ws2s[b * IC + c1];
        }
        const float g0 = xdown[(size_t)kj * IC + c0];
        const float g1 = xdown[(size_t)kj * IC + c1];
        atomicAdd(acc + (size_t)ji * IC + c0, g0 * t0 * s0);
        atomicAdd(acc + (size_t)ji * IC + c1, g1 * t1 * s1);
    }
}

__global__ void zero4_kernel(float4* __restrict__ p, int n4)
{
    const int i = blockIdx.x * blockDim.x + threadIdx.x;
    if (i < n4) p[i] = make_float4(0.f, 0.f, 0.f, 0.f);
}

// ---------------- launch (serial; idx 3 = gemm_kj profiled) ---------------
extern "C" void kernel_launch(void* const* d_in, const int* in_sizes, int n_in,
                              void* d_out, int out_size)
{
    const float* e1     = (const float*)d_in[0];
    const float* rbf    = (const float*)d_in[1];
    const float* sbf    = (const float*)d_in[2];
    const float* tt     = (const float*)d_in[3];
    const int*   idx_kj = (const int*)d_in[4];
    const int*   idx_ji = (const int*)d_in[5];
    const float* W_rbf1 = (const float*)d_in[6];
    const float* W_rbf2 = (const float*)d_in[7];
    const float* W_sbf1 = (const float*)d_in[8];
    const float* W_sbf2 = (const float*)d_in[9];
    const float* W_t1   = (const float*)d_in[10];
    const float* W_t2   = (const float*)d_in[11];
    const float* W_rbf  = (const float*)d_in[12];
    const float* W_kj   = (const float*)d_in[13];
    const float* b_kj   = (const float*)d_in[14];
    const float* W_ji   = (const float*)d_in[15];
    const float* b_ji   = (const float*)d_in[16];
    const float* W_down = (const float*)d_in[17];
    const float* W_up   = (const float*)d_in[18];
    const float* Wb1    = (const float*)d_in[19];
    const float* bb1    = (const float*)d_in[20];
    const float* Wb2    = (const float*)d_in[21];
    const float* bb2    = (const float*)d_in[22];
    const float* W_lin  = (const float*)d_in[23];
    const float* b_lin  = (const float*)d_in[24];
    const float* Wa1    = (const float*)d_in[25];
    const float* ba1    = (const float*)d_in[26];
    const float* Wa2    = (const float*)d_in[27];
    const float* ba2    = (const float*)d_in[28];

    const int E = in_sizes[0] / HH;
    const int T = in_sizes[4];

    float *xji, *rbfh, *rbfh2, *rb8, *xdown, *acc, *t8, *s8, *A, *B, *C;
    cudaGetSymbolAddress((void**)&xji,   g_xji);
    cudaGetSymbolAddress((void**)&rbfh,  g_rbfh);
    cudaGetSymbolAddress((void**)&rbfh2, g_rbfh2);
    cudaGetSymbolAddress((void**)&rb8,   g_rb8);
    cudaGetSymbolAddress((void**)&xdown, g_xdown);
    cudaGetSymbolAddress((void**)&acc,   g_acc);
    cudaGetSymbolAddress((void**)&t8,    g_t8);
    cudaGetSymbolAddress((void**)&s8,    g_s8);
    cudaGetSymbolAddress((void**)&A,     g_bufA);
    cudaGetSymbolAddress((void**)&B,     g_bufB);
    cudaGetSymbolAddress((void**)&C,     g_bufC);

    float* out_e1 = (float*)d_out;
    float* out_e2 = (float*)d_out + (size_t)E * HH;

    const int WS = HH * HH;

    const int sm_hh = 64 * 132 * 4 + 64 * 128 * 8;   // 99328
    const int sm_dn = 64 * 132 * 4 + 64 * 64 * 8;    // 66560
    const int sm_up = 64 * 132 * 4 + 64 * 128 * 8;   // 99328
    cudaFuncSetAttribute(gemm_f2<HH, HH>, cudaFuncAttributeMaxDynamicSharedMemorySize, sm_hh);
    cudaFuncSetAttribute(gemm_f2<HH, IC>, cudaFuncAttributeMaxDynamicSharedMemorySize, sm_dn);
    cudaFuncSetAttribute(gemm_f2<IC, HH>, cudaFuncAttributeMaxDynamicSharedMemorySize, sm_up);

    const int sm_pt = (8 * 320 + 8 * 32 * 33 + 2 * 24 * TK) * 4;    // 100480
    const int sm_ps = (8 * 64 + 8 * 32 * 33 + 2 * 24 * SBFK) * 4;   // 43904
    cudaFuncSetAttribute(proj8cp<TK, 320>, cudaFuncAttributeMaxDynamicSharedMemorySize, sm_pt);
    cudaFuncSetAttribute(proj8cp<SBFK, 64>, cudaFuncAttributeMaxDynamicSharedMemorySize, sm_ps);

    const int gblocks = (E + 127) / 128;

    // serial; launch idx 3 (4th) = gemm_f2<HH,HH> (kj) -> profiled
    rb8_kernel<<<(E + 255) / 256, 256>>>(rbf, W_rbf1, rb8, E);                       // 0
    rbfh_kernel<<<(E + 31) / 32, HH>>>(rb8, rbf, W_rbf2, W_rbf, rbfh, rbfh2, E);     // 1
    proj8cp<SBFK, 64><<<296, 256, sm_ps>>>(sbf, W_sbf1, s8, T);                      // 2
    gemm_f2<HH, HH><<<gblocks, 256, sm_hh>>>(e1, W_kj, b_kj, rbfh, nullptr, A, nullptr, nullptr, E, 1);   // 3 (profiled)
    gemm_f2<HH, IC><<<gblocks, 256, sm_dn>>>(A, W_down, nullptr, nullptr, nullptr, xdown, nullptr, nullptr, E, 1); // 4
    proj8cp<TK, 320><<<296, 256, sm_pt>>>(tt, W_t1, t8, T);                          // 5
    zero4_kernel<<<(E * IC / 4 + 255) / 256, 256>>>((float4*)acc, E * IC / 4);       // 6
    gemm_f2<HH, HH><<<gblocks, 256, sm_hh>>>(e1, W_ji, b_ji, nullptr, nullptr, xji, nullptr, nullptr, E, 1); // 7
    triplet_kernel<<<2368, 256>>>(t8, s8, W_t2, W_sbf2, xdown, idx_kj, idx_ji, acc, T); // 8

    // A = silu(acc @ W_up) + x_ji
    gemm_f2<IC, HH><<<gblocks, 256, sm_up>>>(acc, W_up, nullptr, nullptr, xji, A, nullptr, nullptr, E, 1);
    // residual before (1 layer)
    gemm_f2<HH, HH><<<gblocks, 256, sm_hh>>>(A, Wb1, bb1, nullptr, nullptr, B, nullptr, nullptr, E, 1);
    gemm_f2<HH, HH><<<gblocks, 256, sm_hh>>>(B, Wb2, bb2, nullptr, A, C, nullptr, nullptr, E, 1);
    // h = silu(C @ W_lin + b_lin) + e1
    gemm_f2<HH, HH><<<gblocks, 256, sm_hh>>>(C, W_lin, b_lin, nullptr, e1, A, nullptr, nullptr, E, 1);
    // residual after layer 0
    gemm_f2<HH, HH><<<gblocks, 256, sm_hh>>>(A, Wa1, ba1, nullptr, nullptr, B, nullptr, nullptr, E, 1);
    gemm_f2<HH, HH><<<gblocks, 256, sm_hh>>>(B, Wa2, ba2, nullptr, A, C, nullptr, nullptr, E, 1);
    // residual after layer 1 -> final outputs
    gemm_f2<HH, HH><<<gblocks, 256, sm_hh>>>(C, Wa1 + WS, ba1 + HH, nullptr, nullptr, B, nullptr, nullptr, E, 1);
    gemm_f2<HH, HH><<<gblocks, 256, sm_hh>>>(B, Wa2 + WS, ba2 + HH, nullptr, C, out_e1, rbfh2, out_e2, E, 1);
}

// round 15
// speedup vs baseline: 1.2285x; 1.1916x over previous
#include <cuda_runtime.h>
#include <cstdint>
#include <math.h>

#define EN_MAX 200000
#define TN_MAX 600000
#define HH 128
#define IC 64
#define BSZ 8
#define NRAD 6
#define SBFK 42
#define TK 294

typedef unsigned long long ull;

// ---------------- scratch (device globals; no allocations) ----------------
__device__ float g_xji[EN_MAX * HH];
__device__ float g_rbfh[EN_MAX * HH];
__device__ float g_rbfh2[EN_MAX * HH];
__device__ float g_rb8[EN_MAX * BSZ];
__device__ float g_xdown[EN_MAX * IC];
__device__ float g_acc[EN_MAX * IC];
__device__ float g_t8[TN_MAX * BSZ];
__device__ float g_s8[TN_MAX * BSZ];
__device__ float g_bufA[EN_MAX * HH];
__device__ float g_bufB[EN_MAX * HH];
__device__ float g_bufC[EN_MAX * HH];

__device__ __forceinline__ float silu_f(float x) {
    return x / (1.0f + __expf(-x));
}

// packed f32x2 helpers (FFMA2 path — ptxas never auto-fuses; PTX only)
__device__ __forceinline__ void ffma2(ull& c, ull a, ull b) {
    asm("fma.rn.f32x2 %0, %1, %2, %0;" : "+l"(c) : "l"(a), "l"(b));
}
__device__ __forceinline__ ull dup2(float x) {
    ull r;
    const unsigned int u = __float_as_uint(x);
    asm("mov.b64 %0, {%1, %1};" : "=l"(r) : "r"(u));
    return r;
}
__device__ __forceinline__ void unpack2(ull v, float& lo, float& hi) {
    unsigned int a, b;
    asm("mov.b64 {%0, %1}, %2;" : "=r"(a), "=r"(b) : "l"(v));
    lo = __uint_as_float(a);
    hi = __uint_as_float(b);
}
__device__ __forceinline__ uint32_t smem_u32(const void* p) {
    uint32_t a;
    asm("{ .reg .u64 t; cvta.to.shared.u64 t, %1; cvt.u32.u64 %0, t; }" : "=r"(a) : "l"(p));
    return a;
}

// ---------------- EXACT R3 gemm_rt (FFMA2, 2421-record GEMM) --------------
// out[row, j] = epi( sum_k in[row,k] * W[k,j] )
// Block computes 128 x NOUT; each thread an 8x8 tile held as 8x4 f32x2 pairs.
template <int KIN, int NOUT>
__global__ void __launch_bounds__(NOUT * 2, 2)
gemm_rt(const float* __restrict__ in,
        const float* __restrict__ W,
        const float* __restrict__ bias,
        const float* __restrict__ mulv,
        const float* __restrict__ addv,
        float* __restrict__ out,
        const float* __restrict__ mul2,
        float* __restrict__ out2,
        int nrows, int act)
{
    constexpr int THREADS = NOUT * 2;        // 256 (NOUT=128) or 128 (NOUT=64)
    constexpr int KB = 64;                   // k-chunk
    constexpr int NC = KIN / KB;             // 2 or 1
    constexpr int APITCH = 132;
    constexpr int TPR = THREADS / 128;       // threads per staged A row
    constexpr int KSPAN = KB / TPR;

    extern __shared__ float sm[];
    float* As = sm;                          // [KB][APITCH] k-major
    float* Bs = sm + KB * APITCH;            // [KB][NOUT]

    const int tid = threadIdx.x;
    const int tr = tid / (NOUT / 8);         // thread row group (0..15)
    const int tc = tid % (NOUT / 8);         // thread col group
    const int r0 = blockIdx.x * 128;

    ull acc2[8][4];
    #pragma unroll
    for (int i = 0; i < 8; ++i)
        #pragma unroll
        for (int p = 0; p < 4; ++p) acc2[i][p] = 0ull;

    #pragma unroll
    for (int c = 0; c < NC; ++c) {
        const int c0 = c * KB;
        if (c) __syncthreads();

        // stage A chunk transposed (k-major)
        {
            const int row = tid / TPR;
            const int part = tid % TPR;
            int rclamp = r0 + row;
            if (rclamp >= nrows) rclamp = nrows - 1;
            const float* src = in + (size_t)rclamp * KIN + c0 + part * KSPAN;
            #pragma unroll
            for (int f = 0; f < KSPAN / 4; ++f) {
                const float4 v = *reinterpret_cast<const float4*>(src + f * 4);
                const int kk = part * KSPAN + f * 4;
                As[(kk + 0) * APITCH + row] = v.x;
                As[(kk + 1) * APITCH + row] = v.y;
                As[(kk + 2) * APITCH + row] = v.z;
                As[(kk + 3) * APITCH + row] = v.w;
            }
        }
        // stage B chunk (row-major [KB][NOUT])
        {
            const float4* Wsrc = reinterpret_cast<const float4*>(W + (size_t)c0 * NOUT);
            float4* Bd = reinterpret_cast<float4*>(Bs);
            #pragma unroll
            for (int i = tid; i < KB * NOUT / 4; i += THREADS)
                Bd[i] = Wsrc[i];
        }
        __syncthreads();

        #pragma unroll 4
        for (int k = 0; k < KB; ++k) {
            const float4 a0 = *reinterpret_cast<const float4*>(&As[k * APITCH + tr * 8]);
            const float4 a1 = *reinterpret_cast<const float4*>(&As[k * APITCH + tr * 8 + 4]);
            const ulonglong2 bA = *reinterpret_cast<const ulonglong2*>(&Bs[k * NOUT + tc * 8]);
            const ulonglong2 bB = *reinterpret_cast<const ulonglong2*>(&Bs[k * NOUT + tc * 8 + 4]);
            const float a[8] = {a0.x, a0.y, a0.z, a0.w, a1.x, a1.y, a1.z, a1.w};
            #pragma unroll
            for (int i = 0; i < 8; ++i) {
                const ull ap = dup2(a[i]);
                ffma2(acc2[i][0], ap, bA.x);
                ffma2(acc2[i][1], ap, bA.y);
                ffma2(acc2[i][2], ap, bB.x);
                ffma2(acc2[i][3], ap, bB.y);
            }
        }
    }

    // epilogue
    float bv[8];
    if (bias) {
        const float4 v0 = *reinterpret_cast<const float4*>(bias + tc * 8);
        const float4 v1 = *reinterpret_cast<const float4*>(bias + tc * 8 + 4);
        bv[0]=v0.x; bv[1]=v0.y; bv[2]=v0.z; bv[3]=v0.w;
        bv[4]=v1.x; bv[5]=v1.y; bv[6]=v1.z; bv[7]=v1.w;
    } else {
        #pragma unroll
        for (int j = 0; j < 8; ++j) bv[j] = 0.f;
    }

    #pragma unroll
    for (int i = 0; i < 8; ++i) {
        const int row = r0 + tr * 8 + i;
        if (row >= nrows) break;
        const size_t o = (size_t)row * NOUT + tc * 8;
        float v[8];
        #pragma unroll
        for (int p = 0; p < 4; ++p)
            unpack2(acc2[i][p], v[2 * p], v[2 * p + 1]);
        #pragma unroll
        for (int j = 0; j < 8; ++j) {
            float x = v[j] + bv[j];
            if (act) x = silu_f(x);
            v[j] = x;
        }
        if (mulv) {
            const float4 m0 = *reinterpret_cast<const float4*>(mulv + o);
            const float4 m1 = *reinterpret_cast<const float4*>(mulv + o + 4);
            v[0]*=m0.x; v[1]*=m0.y; v[2]*=m0.z; v[3]*=m0.w;
            v[4]*=m1.x; v[5]*=m1.y; v[6]*=m1.z; v[7]*=m1.w;
        }
        if (addv) {
            const float4 s0 = *reinterpret_cast<const float4*>(addv + o);
            const float4 s1 = *reinterpret_cast<const float4*>(addv + o + 4);
            v[0]+=s0.x; v[1]+=s0.y; v[2]+=s0.z; v[3]+=s0.w;
            v[4]+=s1.x; v[5]+=s1.y; v[6]+=s1.z; v[7]+=s1.w;
        }
        *reinterpret_cast<float4*>(out + o)     = make_float4(v[0], v[1], v[2], v[3]);
        *reinterpret_cast<float4*>(out + o + 4) = make_float4(v[4], v[5], v[6], v[7]);
        if (out2) {
            const float4 m0 = *reinterpret_cast<const float4*>(mul2 + o);
            const float4 m1 = *reinterpret_cast<const float4*>(mul2 + o + 4);
            *reinterpret_cast<float4*>(out2 + o)     = make_float4(v[0]*m0.x, v[1]*m0.y, v[2]*m0.z, v[3]*m0.w);
            *reinterpret_cast<float4*>(out2 + o + 4) = make_float4(v[4]*m1.x, v[5]*m1.y, v[6]*m1.z, v[7]*m1.w);
        }
    }
}

// ---------------- rbf basis helpers ----------------
__global__ void rb8_kernel(const float* __restrict__ rbf, const float* __restrict__ W1,
                           float* __restrict__ out, int n)
{
    const int e = blockIdx.x * blockDim.x + threadIdx.x;
    if (e >= n) return;
    float r[NRAD];
    #pragma unroll
    for (int i = 0; i < NRAD; ++i) r[i] = rbf[(size_t)e * NRAD + i];
    #pragma unroll
    for (int b = 0; b < BSZ; ++b) {
        float s = 0.f;
        #pragma unroll
        for (int i = 0; i < NRAD; ++i) s += r[i] * __ldg(&W1[i * BSZ + b]);
        out[(size_t)e * BSZ + b] = s;
    }
}

__global__ void rbfh_kernel(const float* __restrict__ rb8, const float* __restrict__ rbf,
                            const float* __restrict__ W_rbf2, const float* __restrict__ W_rbf,
                            float* __restrict__ rbfh, float* __restrict__ rbfh2, int n)
{
    __shared__ float w2[BSZ * HH];
    __shared__ float wr[NRAD * HH];
    const int j = threadIdx.x;
    #pragma unroll
    for (int b = 0; b < BSZ; ++b) w2[b * HH + j] = W_rbf2[b * HH + j];
    #pragma unroll
    for (int r = 0; r < NRAD; ++r) wr[r * HH + j] = W_rbf[r * HH + j];
    __syncthreads();

    const int row0 = blockIdx.x * 32;
    for (int rr = 0; rr < 32; ++rr) {
        const int row = row0 + rr;
        if (row >= n) return;
        const float4* rp = reinterpret_cast<const float4*>(rb8 + (size_t)row * BSZ);
        const float4 ra = __ldg(rp), rb = __ldg(rp + 1);
        float a1 = ra.x * w2[0 * HH + j] + ra.y * w2[1 * HH + j] +
                   ra.z * w2[2 * HH + j] + ra.w * w2[3 * HH + j] +
                   rb.x * w2[4 * HH + j] + rb.y * w2[5 * HH + j] +
                   rb.z * w2[6 * HH + j] + rb.w * w2[7 * HH + j];
        float a2 = 0.f;
        #pragma unroll
        for (int r = 0; r < NRAD; ++r) a2 += __ldg(&rbf[(size_t)row * NRAD + r]) * wr[r * HH + j];
        rbfh[(size_t)row * HH + j]  = a1;
        rbfh2[(size_t)row * HH + j] = a2;
    }
}

// ------- T-space proj: cp.async double-buffered tile streamer (R9) --------
template <int K, int PK>
__global__ void __launch_bounds__(256)
proj8cp(const float* __restrict__ X, const float* __restrict__ W1,
        float* __restrict__ out8, int nrows)
{
    constexpr int ROWS = 24;
    constexpr int TILE_F = ROWS * K;
    constexpr int CH = (TILE_F * 4) / 16;
    constexpr int ITERS = (K + 31) / 32;

    extern __shared__ float sm[];
    float* wcm  = sm;
    float* red  = sm + 8 * PK;
    float* buf0 = red + 8 * 32 * 33;
    float* buf1 = buf0 + TILE_F;

    const int tid = threadIdx.x;
    for (int x = tid; x < 8 * PK; x += 256) wcm[x] = 0.f;
    __syncthreads();
    for (int x = tid; x < K * 8; x += 256) {
        const int i = x / 8, b = x % 8;
        wcm[b * PK + i] = W1[x];
    }

    const int warp = tid >> 5, lane = tid & 31;
    const int G = gridDim.x;
    const int ntiles = (nrows + ROWS - 1) / ROWS;
    float* myred = red + warp * (32 * 33);

    const uint32_t b0u = smem_u32(buf0), b1u = smem_u32(buf1);

    int it = 0;
    if ((int)blockIdx.x < ntiles) {
        const char* gsrc = (const char*)X + (size_t)blockIdx.x * (ROWS * K * 4);
        for (int c = tid; c < CH; c += 256)
            asm volatile("cp.async.cg.shared.global [%0], [%1], 16;"
                         :: "r"(b0u + c * 16), "l"(gsrc + (size_t)c * 16));
    }
    asm volatile("cp.async.commit_group;" ::: "memory");

    for (int tt = blockIdx.x; tt < ntiles; tt += G, ++it) {
        float* cur = (it & 1) ? buf1 : buf0;
        const uint32_t nxtu = (it & 1) ? b0u : b1u;
        const int tnext = tt + G;
        if (tnext < ntiles) {
            const char* gsrc = (const char*)X + (size_t)tnext * (ROWS * K * 4);
            for (int c = tid; c < CH; c += 256)
                asm volatile("cp.async.cg.shared.global [%0], [%1], 16;"
                             :: "r"(nxtu + c * 16), "l"(gsrc + (size_t)c * 16));
            asm volatile("cp.async.commit_group;" ::: "memory");
            asm volatile("cp.async.wait_group 1;" ::: "memory");
        } else {
            asm volatile("cp.async.commit_group;" ::: "memory");
            asm volatile("cp.async.wait_group 0;" ::: "memory");
        }
        __syncthreads();

        const int r0 = tt * ROWS;
        float acc[3][BSZ] = {};
        const float* xb = cur + (3 * warp) * K;
        #pragma unroll
        for (int k = 0; k < ITERS; ++k) {
            const int ii = lane + k * 32;
            float x0 = 0.f, x1 = 0.f, x2 = 0.f;
            if (ii < K) { x0 = xb[ii]; x1 = xb[K + ii]; x2 = xb[2 * K + ii]; }
            #pragma unroll
            for (int b = 0; b < BSZ; ++b) {
                const float w = wcm[b * PK + ii];
                acc[0][b] += w * x0; acc[1][b] += w * x1; acc[2][b] += w * x2;
            }
        }
        #pragma unroll
        for (int rr = 0; rr < 3; ++rr)
            #pragma unroll
            for (int b = 0; b < BSZ; ++b)
                myred[lane * 33 + rr * BSZ + b] = acc[rr][b];
        __syncwarp();
        if (lane < 24) {
            float s = 0.f;
            #pragma unroll
            for (int l = 0; l < 32; ++l) s += myred[l * 33 + lane];
            const int row = r0 + 3 * warp + (lane >> 3);
            if (row < nrows)
                out8[(size_t)(r0 + 3 * warp) * BSZ + lane] = s;
        }
        __syncthreads();
    }
}

// ------- triplet gather/scale/scatter (EXACT R2/R3-era version) -----------
__global__ void triplet_kernel(const float* __restrict__ t8, const float* __restrict__ s8,
                               const float* __restrict__ W_t2, const float* __restrict__ W_sbf2,
                               const float* __restrict__ xdown,
                               const int* __restrict__ idx_kj, const int* __restrict__ idx_ji,
                               float* __restrict__ acc, int nt)
{
    __shared__ float wt2s[BSZ * IC];
    __shared__ float ws2s[BSZ * IC];
    const int tid = threadIdx.x;
    for (int i = tid; i < BSZ * IC; i += blockDim.x) { wt2s[i] = W_t2[i]; ws2s[i] = W_sbf2[i]; }
    __syncthreads();

    const int warp = tid >> 5, lane = tid & 31;
    const int total_warps = (blockDim.x * gridDim.x) >> 5;

    for (int tr = blockIdx.x * (blockDim.x >> 5) + warp; tr < nt; tr += total_warps) {
        const float4* tp = reinterpret_cast<const float4*>(t8 + (size_t)tr * BSZ);
        const float4 ta = __ldg(tp), tb = __ldg(tp + 1);
        const float4* sp = reinterpret_cast<const float4*>(s8 + (size_t)tr * BSZ);
        const float4 sa = __ldg(sp), sb = __ldg(sp + 1);
        const float tv[BSZ] = {ta.x, ta.y, ta.z, ta.w, tb.x, tb.y, tb.z, tb.w};
        const float sv[BSZ] = {sa.x, sa.y, sa.z, sa.w, sb.x, sb.y, sb.z, sb.w};
        const int kj = idx_kj[tr], ji = idx_ji[tr];
        const int c0 = lane, c1 = lane + 32;
        float t0 = 0.f, t1 = 0.f, s0 = 0.f, s1 = 0.f;
        #pragma unroll
        for (int b = 0; b < BSZ; ++b) {
            t0 += tv[b] * wt2s[b * IC + c0];
            t1 += tv[b] * wt2s[b * IC + c1];
            s0 += sv[b] * ws2s[b * IC + c0];
            s1 += sv[b] * ws2s[b * IC + c1];
        }
        const float g0 = xdown[(size_t)kj * IC + c0];
        const float g1 = xdown[(size_t)kj * IC + c1];
        atomicAdd(acc + (size_t)ji * IC + c0, g0 * t0 * s0);
        atomicAdd(acc + (size_t)ji * IC + c1, g1 * t1 * s1);
    }
}

__global__ void zero4_kernel(float4* __restrict__ p, int n4)
{
    const int i = blockIdx.x * blockDim.x + threadIdx.x;
    if (i < n4) p[i] = make_float4(0.f, 0.f, 0.f, 0.f);
}

// ---------------- launch (serial; idx 3 = gemm_rt kj profiled) ------------
extern "C" void kernel_launch(void* const* d_in, const int* in_sizes, int n_in,
                              void* d_out, int out_size)
{
    const float* e1     = (const float*)d_in[0];
    const float* rbf    = (const float*)d_in[1];
    const float* sbf    = (const float*)d_in[2];
    const float* tt     = (const float*)d_in[3];
    const int*   idx_kj = (const int*)d_in[4];
    const int*   idx_ji = (const int*)d_in[5];
    const float* W_rbf1 = (const float*)d_in[6];
    const float* W_rbf2 = (const float*)d_in[7];
    const float* W_sbf1 = (const float*)d_in[8];
    const float* W_sbf2 = (const float*)d_in[9];
    const float* W_t1   = (const float*)d_in[10];
    const float* W_t2   = (const float*)d_in[11];
    const float* W_rbf  = (const float*)d_in[12];
    const float* W_kj   = (const float*)d_in[13];
    const float* b_kj   = (const float*)d_in[14];
    const float* W_ji   = (const float*)d_in[15];
    const float* b_ji   = (const float*)d_in[16];
    const float* W_down = (const float*)d_in[17];
    const float* W_up   = (const float*)d_in[18];
    const float* Wb1    = (const float*)d_in[19];
    const float* bb1    = (const float*)d_in[20];
    const float* Wb2    = (const float*)d_in[21];
    const float* bb2    = (const float*)d_in[22];
    const float* W_lin  = (const float*)d_in[23];
    const float* b_lin  = (const float*)d_in[24];
    const float* Wa1    = (const float*)d_in[25];
    const float* ba1    = (const float*)d_in[26];
    const float* Wa2    = (const float*)d_in[27];
    const float* ba2    = (const float*)d_in[28];

    const int E = in_sizes[0] / HH;
    const int T = in_sizes[4];

    float *xji, *rbfh, *rbfh2, *rb8, *xdown, *acc, *t8, *s8, *A, *B, *C;
    cudaGetSymbolAddress((void**)&xji,   g_xji);
    cudaGetSymbolAddress((void**)&rbfh,  g_rbfh);
    cudaGetSymbolAddress((void**)&rbfh2, g_rbfh2);
    cudaGetSymbolAddress((void**)&rb8,   g_rb8);
    cudaGetSymbolAddress((void**)&xdown, g_xdown);
    cudaGetSymbolAddress((void**)&acc,   g_acc);
    cudaGetSymbolAddress((void**)&t8,    g_t8);
    cudaGetSymbolAddress((void**)&s8,    g_s8);
    cudaGetSymbolAddress((void**)&A,     g_bufA);
    cudaGetSymbolAddress((void**)&B,     g_bufB);
    cudaGetSymbolAddress((void**)&C,     g_bufC);

    float* out_e1 = (float*)d_out;
    float* out_e2 = (float*)d_out + (size_t)E * HH;

    const int WS = HH * HH;

    // dynamic smem (R3 sizes): As[64][132] + Bs[64][NOUT], fp32
    const int sm_g128 = 64 * 132 * 4 + 64 * 128 * 4;   // 66560
    const int sm_gd   = 64 * 132 * 4 + 64 * 64 * 4;    // 50176
    const int sm_gu   = 64 * 132 * 4 + 64 * 128 * 4;   // 66560
    cudaFuncSetAttribute(gemm_rt<HH, HH>, cudaFuncAttributeMaxDynamicSharedMemorySize, sm_g128);
    cudaFuncSetAttribute(gemm_rt<HH, IC>, cudaFuncAttributeMaxDynamicSharedMemorySize, sm_gd);
    cudaFuncSetAttribute(gemm_rt<IC, HH>, cudaFuncAttributeMaxDynamicSharedMemorySize, sm_gu);

    const int sm_pt = (8 * 320 + 8 * 32 * 33 + 2 * 24 * TK) * 4;    // 100480
    const int sm_ps = (8 * 64 + 8 * 32 * 33 + 2 * 24 * SBFK) * 4;   // 43904
    cudaFuncSetAttribute(proj8cp<TK, 320>, cudaFuncAttributeMaxDynamicSharedMemorySize, sm_pt);
    cudaFuncSetAttribute(proj8cp<SBFK, 64>, cudaFuncAttributeMaxDynamicSharedMemorySize, sm_ps);

    const int gblocks = (E + 127) / 128;

    // serial; launch idx 3 (4th) = gemm_rt<HH,HH> (kj) -> profiled
    rb8_kernel<<<(E + 255) / 256, 256>>>(rbf, W_rbf1, rb8, E);                       // 0
    rbfh_kernel<<<(E + 31) / 32, HH>>>(rb8, rbf, W_rbf2, W_rbf, rbfh, rbfh2, E);     // 1
    proj8cp<SBFK, 64><<<296, 256, sm_ps>>>(sbf, W_sbf1, s8, T);                      // 2
    gemm_rt<HH, HH><<<gblocks, 256, sm_g128>>>(e1, W_kj, b_kj, rbfh, nullptr, A, nullptr, nullptr, E, 1);   // 3 (profiled)
    gemm_rt<HH, IC><<<gblocks, 128, sm_gd>>>(A, W_down, nullptr, nullptr, nullptr, xdown, nullptr, nullptr, E, 1); // 4
    proj8cp<TK, 320><<<296, 256, sm_pt>>>(tt, W_t1, t8, T);                          // 5
    zero4_kernel<<<(E * IC / 4 + 255) / 256, 256>>>((float4*)acc, E * IC / 4);       // 6
    gemm_rt<HH, HH><<<gblocks, 256, sm_g128>>>(e1, W_ji, b_ji, nullptr, nullptr, xji, nullptr, nullptr, E, 1); // 7
    triplet_kernel<<<2368, 256>>>(t8, s8, W_t2, W_sbf2, xdown, idx_kj, idx_ji, acc, T); // 8

    // A = silu(acc @ W_up) + x_ji
    gemm_rt<IC, HH><<<gblocks, 256, sm_gu>>>(acc, W_up, nullptr, nullptr, xji, A, nullptr, nullptr, E, 1);
    // residual before (1 layer)
    gemm_rt<HH, HH><<<gblocks, 256, sm_g128>>>(A, Wb1, bb1, nullptr, nullptr, B, nullptr, nullptr, E, 1);
    gemm_rt<HH, HH><<<gblocks, 256, sm_g128>>>(B, Wb2, bb2, nullptr, A, C, nullptr, nullptr, E, 1);
    // h = silu(C @ W_lin + b_lin) + e1
    gemm_rt<HH, HH><<<gblocks, 256, sm_g128>>>(C, W_lin, b_lin, nullptr, e1, A, nullptr, nullptr, E, 1);
    // residual after layer 0
    gemm_rt<HH, HH><<<gblocks, 256, sm_g128>>>(A, Wa1, ba1, nullptr, nullptr, B, nullptr, nullptr, E, 1);
    gemm_rt<HH, HH><<<gblocks, 256, sm_g128>>>(B, Wa2, ba2, nullptr, A, C, nullptr, nullptr, E, 1);
    // residual after layer 1 -> final outputs
    gemm_rt<HH, HH><<<gblocks, 256, sm_g128>>>(C, Wa1 + WS, ba1 + HH, nullptr, nullptr, B, nullptr, nullptr, E, 1);
    gemm_rt<HH, HH><<<gblocks, 256, sm_g128>>>(B, Wa2 + WS, ba2 + HH, nullptr, C, out_e1, rbfh2, out_e2, E, 1);
}

// round 16
// speedup vs baseline: 1.2355x; 1.0057x over previous
#include <cuda_runtime.h>
#include <cstdint>
#include <math.h>

#define EN_MAX 200000
#define TN_MAX 600000
#define HH 128
#define IC 64
#define BSZ 8
#define NRAD 6
#define SBFK 42
#define TK 294

typedef unsigned long long ull;

// ---------------- scratch (device globals; no allocations) ----------------
__device__ float g_xji[EN_MAX * HH];
__device__ float g_rbfh[EN_MAX * HH];
__device__ float g_rbfh2[EN_MAX * HH];
__device__ float g_rb8[EN_MAX * BSZ];
__device__ float g_xdown[EN_MAX * IC];
__device__ float g_acc[EN_MAX * IC];
__device__ float g_t8[TN_MAX * BSZ];
__device__ float g_s8[TN_MAX * BSZ];
__device__ float g_bufA[EN_MAX * HH];
__device__ float g_bufB[EN_MAX * HH];
__device__ float g_bufC[EN_MAX * HH];

__device__ __forceinline__ float silu_f(float x) {
    return x / (1.0f + __expf(-x));
}

// packed f32x2 helpers (FFMA2 path — ptxas never auto-fuses; PTX only)
__device__ __forceinline__ void ffma2(ull& c, ull a, ull b) {
    asm("fma.rn.f32x2 %0, %1, %2, %0;" : "+l"(c) : "l"(a), "l"(b));
}
__device__ __forceinline__ ull dup2(float x) {
    ull r;
    const unsigned int u = __float_as_uint(x);
    asm("mov.b64 %0, {%1, %1};" : "=l"(r) : "r"(u));
    return r;
}
__device__ __forceinline__ void unpack2(ull v, float& lo, float& hi) {
    unsigned int a, b;
    asm("mov.b64 {%0, %1}, %2;" : "=r"(a), "=r"(b) : "l"(v));
    lo = __uint_as_float(a);
    hi = __uint_as_float(b);
}
__device__ __forceinline__ uint32_t smem_u32(const void* p) {
    uint32_t a;
    asm("{ .reg .u64 t; cvta.to.shared.u64 t, %1; cvt.u32.u64 %0, t; }" : "=r"(a) : "l"(p));
    return a;
}

// ---------------- EXACT R3 gemm_rt (FFMA2, 2421-record GEMM) --------------
template <int KIN, int NOUT>
__global__ void __launch_bounds__(NOUT * 2, 2)
gemm_rt(const float* __restrict__ in,
        const float* __restrict__ W,
        const float* __restrict__ bias,
        const float* __restrict__ mulv,
        const float* __restrict__ addv,
        float* __restrict__ out,
        const float* __restrict__ mul2,
        float* __restrict__ out2,
        int nrows, int act)
{
    constexpr int THREADS = NOUT * 2;
    constexpr int KB = 64;
    constexpr int NC = KIN / KB;
    constexpr int APITCH = 132;
    constexpr int TPR = THREADS / 128;
    constexpr int KSPAN = KB / TPR;

    extern __shared__ float sm[];
    float* As = sm;                          // [KB][APITCH] k-major
    float* Bs = sm + KB * APITCH;            // [KB][NOUT]

    const int tid = threadIdx.x;
    const int tr = tid / (NOUT / 8);
    const int tc = tid % (NOUT / 8);
    const int r0 = blockIdx.x * 128;

    ull acc2[8][4];
    #pragma unroll
    for (int i = 0; i < 8; ++i)
        #pragma unroll
        for (int p = 0; p < 4; ++p) acc2[i][p] = 0ull;

    #pragma unroll
    for (int c = 0; c < NC; ++c) {
        const int c0 = c * KB;
        if (c) __syncthreads();

        {
            const int row = tid / TPR;
            const int part = tid % TPR;
            int rclamp = r0 + row;
            if (rclamp >= nrows) rclamp = nrows - 1;
            const float* src = in + (size_t)rclamp * KIN + c0 + part * KSPAN;
            #pragma unroll
            for (int f = 0; f < KSPAN / 4; ++f) {
                const float4 v = *reinterpret_cast<const float4*>(src + f * 4);
                const int kk = part * KSPAN + f * 4;
                As[(kk + 0) * APITCH + row] = v.x;
                As[(kk + 1) * APITCH + row] = v.y;
                As[(kk + 2) * APITCH + row] = v.z;
                As[(kk + 3) * APITCH + row] = v.w;
            }
        }
        {
            const float4* Wsrc = reinterpret_cast<const float4*>(W + (size_t)c0 * NOUT);
            float4* Bd = reinterpret_cast<float4*>(Bs);
            #pragma unroll
            for (int i = tid; i < KB * NOUT / 4; i += THREADS)
                Bd[i] = Wsrc[i];
        }
        __syncthreads();

        #pragma unroll 4
        for (int k = 0; k < KB; ++k) {
            const float4 a0 = *reinterpret_cast<const float4*>(&As[k * APITCH + tr * 8]);
            const float4 a1 = *reinterpret_cast<const float4*>(&As[k * APITCH + tr * 8 + 4]);
            const ulonglong2 bA = *reinterpret_cast<const ulonglong2*>(&Bs[k * NOUT + tc * 8]);
            const ulonglong2 bB = *reinterpret_cast<const ulonglong2*>(&Bs[k * NOUT + tc * 8 + 4]);
            const float a[8] = {a0.x, a0.y, a0.z, a0.w, a1.x, a1.y, a1.z, a1.w};
            #pragma unroll
            for (int i = 0; i < 8; ++i) {
                const ull ap = dup2(a[i]);
                ffma2(acc2[i][0], ap, bA.x);
                ffma2(acc2[i][1], ap, bA.y);
                ffma2(acc2[i][2], ap, bB.x);
                ffma2(acc2[i][3], ap, bB.y);
            }
        }
    }

    float bv[8];
    if (bias) {
        const float4 v0 = *reinterpret_cast<const float4*>(bias + tc * 8);
        const float4 v1 = *reinterpret_cast<const float4*>(bias + tc * 8 + 4);
        bv[0]=v0.x; bv[1]=v0.y; bv[2]=v0.z; bv[3]=v0.w;
        bv[4]=v1.x; bv[5]=v1.y; bv[6]=v1.z; bv[7]=v1.w;
    } else {
        #pragma unroll
        for (int j = 0; j < 8; ++j) bv[j] = 0.f;
    }

    #pragma unroll
    for (int i = 0; i < 8; ++i) {
        const int row = r0 + tr * 8 + i;
        if (row >= nrows) break;
        const size_t o = (size_t)row * NOUT + tc * 8;
        float v[8];
        #pragma unroll
        for (int p = 0; p < 4; ++p)
            unpack2(acc2[i][p], v[2 * p], v[2 * p + 1]);
        #pragma unroll
        for (int j = 0; j < 8; ++j) {
            float x = v[j] + bv[j];
            if (act) x = silu_f(x);
            v[j] = x;
        }
        if (mulv) {
            const float4 m0 = *reinterpret_cast<const float4*>(mulv + o);
            const float4 m1 = *reinterpret_cast<const float4*>(mulv + o + 4);
            v[0]*=m0.x; v[1]*=m0.y; v[2]*=m0.z; v[3]*=m0.w;
            v[4]*=m1.x; v[5]*=m1.y; v[6]*=m1.z; v[7]*=m1.w;
        }
        if (addv) {
            const float4 s0 = *reinterpret_cast<const float4*>(addv + o);
            const float4 s1 = *reinterpret_cast<const float4*>(addv + o + 4);
            v[0]+=s0.x; v[1]+=s0.y; v[2]+=s0.z; v[3]+=s0.w;
            v[4]+=s1.x; v[5]+=s1.y; v[6]+=s1.z; v[7]+=s1.w;
        }
        *reinterpret_cast<float4*>(out + o)     = make_float4(v[0], v[1], v[2], v[3]);
        *reinterpret_cast<float4*>(out + o + 4) = make_float4(v[4], v[5], v[6], v[7]);
        if (out2) {
            const float4 m0 = *reinterpret_cast<const float4*>(mul2 + o);
            const float4 m1 = *reinterpret_cast<const float4*>(mul2 + o + 4);
            *reinterpret_cast<float4*>(out2 + o)     = make_float4(v[0]*m0.x, v[1]*m0.y, v[2]*m0.z, v[3]*m0.w);
            *reinterpret_cast<float4*>(out2 + o + 4) = make_float4(v[4]*m1.x, v[5]*m1.y, v[6]*m1.z, v[7]*m1.w);
        }
    }
}

// ---------------- rbf basis helpers ----------------
__global__ void rb8_kernel(const float* __restrict__ rbf, const float* __restrict__ W1,
                           float* __restrict__ out, int n)
{
    const int e = blockIdx.x * blockDim.x + threadIdx.x;
    if (e >= n) return;
    float r[NRAD];
    #pragma unroll
    for (int i = 0; i < NRAD; ++i) r[i] = rbf[(size_t)e * NRAD + i];
    #pragma unroll
    for (int b = 0; b < BSZ; ++b) {
        float s = 0.f;
        #pragma unroll
        for (int i = 0; i < NRAD; ++i) s += r[i] * __ldg(&W1[i * BSZ + b]);
        out[(size_t)e * BSZ + b] = s;
    }
}

__global__ void rbfh_kernel(const float* __restrict__ rb8, const float* __restrict__ rbf,
                            const float* __restrict__ W_rbf2, const float* __restrict__ W_rbf,
                            float* __restrict__ rbfh, float* __restrict__ rbfh2, int n)
{
    __shared__ float w2[BSZ * HH];
    __shared__ float wr[NRAD * HH];
    const int j = threadIdx.x;
    #pragma unroll
    for (int b = 0; b < BSZ; ++b) w2[b * HH + j] = W_rbf2[b * HH + j];
    #pragma unroll
    for (int r = 0; r < NRAD; ++r) wr[r * HH + j] = W_rbf[r * HH + j];
    __syncthreads();

    const int row0 = blockIdx.x * 32;
    for (int rr = 0; rr < 32; ++rr) {
        const int row = row0 + rr;
        if (row >= n) return;
        const float4* rp = reinterpret_cast<const float4*>(rb8 + (size_t)row * BSZ);
        const float4 ra = __ldg(rp), rb = __ldg(rp + 1);
        float a1 = ra.x * w2[0 * HH + j] + ra.y * w2[1 * HH + j] +
                   ra.z * w2[2 * HH + j] + ra.w * w2[3 * HH + j] +
                   rb.x * w2[4 * HH + j] + rb.y * w2[5 * HH + j] +
                   rb.z * w2[6 * HH + j] + rb.w * w2[7 * HH + j];
        float a2 = 0.f;
        #pragma unroll
        for (int r = 0; r < NRAD; ++r) a2 += __ldg(&rbf[(size_t)row * NRAD + r]) * wr[r * HH + j];
        rbfh[(size_t)row * HH + j]  = a1;
        rbfh2[(size_t)row * HH + j] = a2;
    }
}

// ------- T-space proj: cp.async double-buffered tile streamer (R9) --------
template <int K, int PK>
__global__ void __launch_bounds__(256)
proj8cp(const float* __restrict__ X, const float* __restrict__ W1,
        float* __restrict__ out8, int nrows)
{
    constexpr int ROWS = 24;
    constexpr int TILE_F = ROWS * K;
    constexpr int CH = (TILE_F * 4) / 16;
    constexpr int ITERS = (K + 31) / 32;

    extern __shared__ float sm[];
    float* wcm  = sm;
    float* red  = sm + 8 * PK;
    float* buf0 = red + 8 * 32 * 33;
    float* buf1 = buf0 + TILE_F;

    const int tid = threadIdx.x;
    for (int x = tid; x < 8 * PK; x += 256) wcm[x] = 0.f;
    __syncthreads();
    for (int x = tid; x < K * 8; x += 256) {
        const int i = x / 8, b = x % 8;
        wcm[b * PK + i] = W1[x];
    }

    const int warp = tid >> 5, lane = tid & 31;
    const int G = gridDim.x;
    const int ntiles = (nrows + ROWS - 1) / ROWS;
    float* myred = red + warp * (32 * 33);

    const uint32_t b0u = smem_u32(buf0), b1u = smem_u32(buf1);

    int it = 0;
    if ((int)blockIdx.x < ntiles) {
        const char* gsrc = (const char*)X + (size_t)blockIdx.x * (ROWS * K * 4);
        for (int c = tid; c < CH; c += 256)
            asm volatile("cp.async.cg.shared.global [%0], [%1], 16;"
                         :: "r"(b0u + c * 16), "l"(gsrc + (size_t)c * 16));
    }
    asm volatile("cp.async.commit_group;" ::: "memory");

    for (int tt = blockIdx.x; tt < ntiles; tt += G, ++it) {
        float* cur = (it & 1) ? buf1 : buf0;
        const uint32_t nxtu = (it & 1) ? b0u : b1u;
        const int tnext = tt + G;
        if (tnext < ntiles) {
            const char* gsrc = (const char*)X + (size_t)tnext * (ROWS * K * 4);
            for (int c = tid; c < CH; c += 256)
                asm volatile("cp.async.cg.shared.global [%0], [%1], 16;"
                             :: "r"(nxtu + c * 16), "l"(gsrc + (size_t)c * 16));
            asm volatile("cp.async.commit_group;" ::: "memory");
            asm volatile("cp.async.wait_group 1;" ::: "memory");
        } else {
            asm volatile("cp.async.commit_group;" ::: "memory");
            asm volatile("cp.async.wait_group 0;" ::: "memory");
        }
        __syncthreads();

        const int r0 = tt * ROWS;
        float acc[3][BSZ] = {};
        const float* xb = cur + (3 * warp) * K;
        #pragma unroll
        for (int k = 0; k < ITERS; ++k) {
            const int ii = lane + k * 32;
            float x0 = 0.f, x1 = 0.f, x2 = 0.f;
            if (ii < K) { x0 = xb[ii]; x1 = xb[K + ii]; x2 = xb[2 * K + ii]; }
            #pragma unroll
            for (int b = 0; b < BSZ; ++b) {
                const float w = wcm[b * PK + ii];
                acc[0][b] += w * x0; acc[1][b] += w * x1; acc[2][b] += w * x2;
            }
        }
        #pragma unroll
        for (int rr = 0; rr < 3; ++rr)
            #pragma unroll
            for (int b = 0; b < BSZ; ++b)
                myred[lane * 33 + rr * BSZ + b] = acc[rr][b];
        __syncwarp();
        if (lane < 24) {
            float s = 0.f;
            #pragma unroll
            for (int l = 0; l < 32; ++l) s += myred[l * 33 + lane];
            const int row = r0 + 3 * warp + (lane >> 3);
            if (row < nrows)
                out8[(size_t)(r0 + 3 * warp) * BSZ + lane] = s;
        }
        __syncthreads();
    }
}

// ------- triplet gather/scale/scatter (EXACT R2/R3-era version) -----------
__global__ void triplet_kernel(const float* __restrict__ t8, const float* __restrict__ s8,
                               const float* __restrict__ W_t2, const float* __restrict__ W_sbf2,
                               const float* __restrict__ xdown,
                               const int* __restrict__ idx_kj, const int* __restrict__ idx_ji,
                               float* __restrict__ acc, int nt)
{
    __shared__ float wt2s[BSZ * IC];
    __shared__ float ws2s[BSZ * IC];
    const int tid = threadIdx.x;
    for (int i = tid; i < BSZ * IC; i += blockDim.x) { wt2s[i] = W_t2[i]; ws2s[i] = W_sbf2[i]; }
    __syncthreads();

    const int warp = tid >> 5, lane = tid & 31;
    const int total_warps = (blockDim.x * gridDim.x) >> 5;

    for (int tr = blockIdx.x * (blockDim.x >> 5) + warp; tr < nt; tr += total_warps) {
        const float4* tp = reinterpret_cast<const float4*>(t8 + (size_t)tr * BSZ);
        const float4 ta = __ldg(tp), tb = __ldg(tp + 1);
        const float4* sp = reinterpret_cast<const float4*>(s8 + (size_t)tr * BSZ);
        const float4 sa = __ldg(sp), sb = __ldg(sp + 1);
        const float tv[BSZ] = {ta.x, ta.y, ta.z, ta.w, tb.x, tb.y, tb.z, tb.w};
        const float sv[BSZ] = {sa.x, sa.y, sa.z, sa.w, sb.x, sb.y, sb.z, sb.w};
        const int kj = idx_kj[tr], ji = idx_ji[tr];
        const int c0 = lane, c1 = lane + 32;
        float t0 = 0.f, t1 = 0.f, s0 = 0.f, s1 = 0.f;
        #pragma unroll
        for (int b = 0; b < BSZ; ++b) {
            t0 += tv[b] * wt2s[b * IC + c0];
            t1 += tv[b] * wt2s[b * IC + c1];
            s0 += sv[b] * ws2s[b * IC + c0];
            s1 += sv[b] * ws2s[b * IC + c1];
        }
        const float g0 = xdown[(size_t)kj * IC + c0];
        const float g1 = xdown[(size_t)kj * IC + c1];
        atomicAdd(acc + (size_t)ji * IC + c0, g0 * t0 * s0);
        atomicAdd(acc + (size_t)ji * IC + c1, g1 * t1 * s1);
    }
}

__global__ void zero4_kernel(float4* __restrict__ p, int n4)
{
    const int i = blockIdx.x * blockDim.x + threadIdx.x;
    if (i < n4) p[i] = make_float4(0.f, 0.f, 0.f, 0.f);
}

// ---------------- streams/events (host objects; created pre-run) ----------
struct HxStreams {
    cudaStream_t s2;
    cudaEvent_t evF, evJ;
    HxStreams() {
        cudaStreamCreateWithFlags(&s2, cudaStreamNonBlocking);
        cudaEventCreateWithFlags(&evF, cudaEventDisableTiming);
        cudaEventCreateWithFlags(&evJ, cudaEventDisableTiming);
    }
};
static HxStreams g_hx;

// ---------------- launch: serial R14 + narrow ji || triplet overlap -------
extern "C" void kernel_launch(void* const* d_in, const int* in_sizes, int n_in,
                              void* d_out, int out_size)
{
    const float* e1     = (const float*)d_in[0];
    const float* rbf    = (const float*)d_in[1];
    const float* sbf    = (const float*)d_in[2];
    const float* tt     = (const float*)d_in[3];
    const int*   idx_kj = (const int*)d_in[4];
    const int*   idx_ji = (const int*)d_in[5];
    const float* W_rbf1 = (const float*)d_in[6];
    const float* W_rbf2 = (const float*)d_in[7];
    const float* W_sbf1 = (const float*)d_in[8];
    const float* W_sbf2 = (const float*)d_in[9];
    const float* W_t1   = (const float*)d_in[10];
    const float* W_t2   = (const float*)d_in[11];
    const float* W_rbf  = (const float*)d_in[12];
    const float* W_kj   = (const float*)d_in[13];
    const float* b_kj   = (const float*)d_in[14];
    const float* W_ji   = (const float*)d_in[15];
    const float* b_ji   = (const float*)d_in[16];
    const float* W_down = (const float*)d_in[17];
    const float* W_up   = (const float*)d_in[18];
    const float* Wb1    = (const float*)d_in[19];
    const float* bb1    = (const float*)d_in[20];
    const float* Wb2    = (const float*)d_in[21];
    const float* bb2    = (const float*)d_in[22];
    const float* W_lin  = (const float*)d_in[23];
    const float* b_lin  = (const float*)d_in[24];
    const float* Wa1    = (const float*)d_in[25];
    const float* ba1    = (const float*)d_in[26];
    const float* Wa2    = (const float*)d_in[27];
    const float* ba2    = (const float*)d_in[28];

    const int E = in_sizes[0] / HH;
    const int T = in_sizes[4];

    float *xji, *rbfh, *rbfh2, *rb8, *xdown, *acc, *t8, *s8, *A, *B, *C;
    cudaGetSymbolAddress((void**)&xji,   g_xji);
    cudaGetSymbolAddress((void**)&rbfh,  g_rbfh);
    cudaGetSymbolAddress((void**)&rbfh2, g_rbfh2);
    cudaGetSymbolAddress((void**)&rb8,   g_rb8);
    cudaGetSymbolAddress((void**)&xdown, g_xdown);
    cudaGetSymbolAddress((void**)&acc,   g_acc);
    cudaGetSymbolAddress((void**)&t8,    g_t8);
    cudaGetSymbolAddress((void**)&s8,    g_s8);
    cudaGetSymbolAddress((void**)&A,     g_bufA);
    cudaGetSymbolAddress((void**)&B,     g_bufB);
    cudaGetSymbolAddress((void**)&C,     g_bufC);

    float* out_e1 = (float*)d_out;
    float* out_e2 = (float*)d_out + (size_t)E * HH;

    const int WS = HH * HH;

    const int sm_g128 = 64 * 132 * 4 + 64 * 128 * 4;   // 66560
    const int sm_gd   = 64 * 132 * 4 + 64 * 64 * 4;    // 50176
    const int sm_gu   = 64 * 132 * 4 + 64 * 128 * 4;   // 66560
    cudaFuncSetAttribute(gemm_rt<HH, HH>, cudaFuncAttributeMaxDynamicSharedMemorySize, sm_g128);
    cudaFuncSetAttribute(gemm_rt<HH, IC>, cudaFuncAttributeMaxDynamicSharedMemorySize, sm_gd);
    cudaFuncSetAttribute(gemm_rt<IC, HH>, cudaFuncAttributeMaxDynamicSharedMemorySize, sm_gu);

    const int sm_pt = (8 * 320 + 8 * 32 * 33 + 2 * 24 * TK) * 4;    // 100480
    const int sm_ps = (8 * 64 + 8 * 32 * 33 + 2 * 24 * SBFK) * 4;   // 43904
    cudaFuncSetAttribute(proj8cp<TK, 320>, cudaFuncAttributeMaxDynamicSharedMemorySize, sm_pt);
    cudaFuncSetAttribute(proj8cp<SBFK, 64>, cudaFuncAttributeMaxDynamicSharedMemorySize, sm_ps);

    const int gblocks = (E + 127) / 128;
    cudaStream_t s2 = g_hx.s2;

    // serial prefix on main stream; idx 3 (4th launch) = gemm_rt<HH,IC> (dn)
    rb8_kernel<<<(E + 255) / 256, 256>>>(rbf, W_rbf1, rb8, E);                       // 0
    rbfh_kernel<<<(E + 31) / 32, HH>>>(rb8, rbf, W_rbf2, W_rbf, rbfh, rbfh2, E);     // 1
    gemm_rt<HH, HH><<<gblocks, 256, sm_g128>>>(e1, W_kj, b_kj, rbfh, nullptr, A, nullptr, nullptr, E, 1);   // 2
    gemm_rt<HH, IC><<<gblocks, 128, sm_gd>>>(A, W_down, nullptr, nullptr, nullptr, xdown, nullptr, nullptr, E, 1); // 3 (profiled)
    proj8cp<SBFK, 64><<<296, 256, sm_ps>>>(sbf, W_sbf1, s8, T);                      // 4
    proj8cp<TK, 320><<<296, 256, sm_pt>>>(tt, W_t1, t8, T);                          // 5
    zero4_kernel<<<(E * IC / 4 + 255) / 256, 256>>>((float4*)acc, E * IC / 4);       // 6

    // ---- fork: ji on s2 || triplet on main ----
    cudaEventRecord(g_hx.evF, 0);
    cudaStreamWaitEvent(s2, g_hx.evF, 0);
    gemm_rt<HH, HH><<<gblocks, 256, sm_g128, s2>>>(e1, W_ji, b_ji, nullptr, nullptr, xji, nullptr, nullptr, E, 1); // 7 (s2)
    cudaEventRecord(g_hx.evJ, s2);
    triplet_kernel<<<2368, 256>>>(t8, s8, W_t2, W_sbf2, xdown, idx_kj, idx_ji, acc, T);  // 8 (main)
    cudaStreamWaitEvent(0, g_hx.evJ, 0);
    // ---- join ----

    // A = silu(acc @ W_up) + x_ji
    gemm_rt<IC, HH><<<gblocks, 256, sm_gu>>>(acc, W_up, nullptr, nullptr, xji, A, nullptr, nullptr, E, 1);
    // residual before (1 layer)
    gemm_rt<HH, HH><<<gblocks, 256, sm_g128>>>(A, Wb1, bb1, nullptr, nullptr, B, nullptr, nullptr, E, 1);
    gemm_rt<HH, HH><<<gblocks, 256, sm_g128>>>(B, Wb2, bb2, nullptr, A, C, nullptr, nullptr, E, 1);
    // h = silu(C @ W_lin + b_lin) + e1
    gemm_rt<HH, HH><<<gblocks, 256, sm_g128>>>(C, W_lin, b_lin, nullptr, e1, A, nullptr, nullptr, E, 1);
    // residual after layer 0
    gemm_rt<HH, HH><<<gblocks, 256, sm_g128>>>(A, Wa1, ba1, nullptr, nullptr, B, nullptr, nullptr, E, 1);
    gemm_rt<HH, HH><<<gblocks, 256, sm_g128>>>(B, Wa2, ba2, nullptr, A, C, nullptr, nullptr, E, 1);
    // residual after layer 1 -> final outputs
    gemm_rt<HH, HH><<<gblocks, 256, sm_g128>>>(C, Wa1 + WS, ba1 + HH, nullptr, nullptr, B, nullptr, nullptr, E, 1);
    gemm_rt<HH, HH><<<gblocks, 256, sm_g128>>>(B, Wa2 + WS, ba2 + HH, nullptr, C, out_e1, rbfh2, out_e2, E, 1);
}

// round 17
// speedup vs baseline: 1.2592x; 1.0192x over previous
#include <cuda_runtime.h>
#include <cstdint>
#include <math.h>

#define EN_MAX 200000
#define TN_MAX 600000
#define HH 128
#define IC 64
#define BSZ 8
#define NRAD 6
#define SBFK 42
#define TK 294

typedef unsigned long long ull;

// ---------------- scratch (device globals; no allocations) ----------------
__device__ float g_xji[EN_MAX * HH];
__device__ float g_rbfh[EN_MAX * HH];
__device__ float g_rbfh2[EN_MAX * HH];
__device__ float g_rb8[EN_MAX * BSZ];
__device__ float g_xdown[EN_MAX * IC];
__device__ float g_acc[EN_MAX * IC];
__device__ float g_t8[TN_MAX * BSZ];
__device__ float g_s8[TN_MAX * BSZ];
__device__ float g_bufA[EN_MAX * HH];
__device__ float g_bufB[EN_MAX * HH];
__device__ float g_bufC[EN_MAX * HH];

__device__ __forceinline__ float silu_f(float x) {
    return x / (1.0f + __expf(-x));
}

// packed f32x2 helpers (FFMA2 path — ptxas never auto-fuses; PTX only)
__device__ __forceinline__ void ffma2(ull& c, ull a, ull b) {
    asm("fma.rn.f32x2 %0, %1, %2, %0;" : "+l"(c) : "l"(a), "l"(b));
}
__device__ __forceinline__ ull dup2(float x) {
    ull r;
    const unsigned int u = __float_as_uint(x);
    asm("mov.b64 %0, {%1, %1};" : "=l"(r) : "r"(u));
    return r;
}
__device__ __forceinline__ void unpack2(ull v, float& lo, float& hi) {
    unsigned int a, b;
    asm("mov.b64 {%0, %1}, %2;" : "=r"(a), "=r"(b) : "l"(v));
    lo = __uint_as_float(a);
    hi = __uint_as_float(b);
}
__device__ __forceinline__ uint32_t smem_u32(const void* p) {
    uint32_t a;
    asm("{ .reg .u64 t; cvta.to.shared.u64 t, %1; cvt.u32.u64 %0, t; }" : "=r"(a) : "l"(p));
    return a;
}

// ---------------- EXACT R3 gemm_rt (FFMA2, record GEMM) -------------------
template <int KIN, int NOUT>
__global__ void __launch_bounds__(NOUT * 2, 2)
gemm_rt(const float* __restrict__ in,
        const float* __restrict__ W,
        const float* __restrict__ bias,
        const float* __restrict__ mulv,
        const float* __restrict__ addv,
        float* __restrict__ out,
        const float* __restrict__ mul2,
        float* __restrict__ out2,
        int nrows, int act)
{
    constexpr int THREADS = NOUT * 2;
    constexpr int KB = 64;
    constexpr int NC = KIN / KB;
    constexpr int APITCH = 132;
    constexpr int TPR = THREADS / 128;
    constexpr int KSPAN = KB / TPR;

    extern __shared__ float sm[];
    float* As = sm;                          // [KB][APITCH] k-major
    float* Bs = sm + KB * APITCH;            // [KB][NOUT]

    const int tid = threadIdx.x;
    const int tr = tid / (NOUT / 8);
    const int tc = tid % (NOUT / 8);
    const int r0 = blockIdx.x * 128;

    ull acc2[8][4];
    #pragma unroll
    for (int i = 0; i < 8; ++i)
        #pragma unroll
        for (int p = 0; p < 4; ++p) acc2[i][p] = 0ull;

    #pragma unroll
    for (int c = 0; c < NC; ++c) {
        const int c0 = c * KB;
        if (c) __syncthreads();

        {
            const int row = tid / TPR;
            const int part = tid % TPR;
            int rclamp = r0 + row;
            if (rclamp >= nrows) rclamp = nrows - 1;
            const float* src = in + (size_t)rclamp * KIN + c0 + part * KSPAN;
            #pragma unroll
            for (int f = 0; f < KSPAN / 4; ++f) {
                const float4 v = *reinterpret_cast<const float4*>(src + f * 4);
                const int kk = part * KSPAN + f * 4;
                As[(kk + 0) * APITCH + row] = v.x;
                As[(kk + 1) * APITCH + row] = v.y;
                As[(kk + 2) * APITCH + row] = v.z;
                As[(kk + 3) * APITCH + row] = v.w;
            }
        }
        {
            const float4* Wsrc = reinterpret_cast<const float4*>(W + (size_t)c0 * NOUT);
            float4* Bd = reinterpret_cast<float4*>(Bs);
            #pragma unroll
            for (int i = tid; i < KB * NOUT / 4; i += THREADS)
                Bd[i] = Wsrc[i];
        }
        __syncthreads();

        #pragma unroll 4
        for (int k = 0; k < KB; ++k) {
            const float4 a0 = *reinterpret_cast<const float4*>(&As[k * APITCH + tr * 8]);
            const float4 a1 = *reinterpret_cast<const float4*>(&As[k * APITCH + tr * 8 + 4]);
            const ulonglong2 bA = *reinterpret_cast<const ulonglong2*>(&Bs[k * NOUT + tc * 8]);
            const ulonglong2 bB = *reinterpret_cast<const ulonglong2*>(&Bs[k * NOUT + tc * 8 + 4]);
            const float a[8] = {a0.x, a0.y, a0.z, a0.w, a1.x, a1.y, a1.z, a1.w};
            #pragma unroll
            for (int i = 0; i < 8; ++i) {
                const ull ap = dup2(a[i]);
                ffma2(acc2[i][0], ap, bA.x);
                ffma2(acc2[i][1], ap, bA.y);
                ffma2(acc2[i][2], ap, bB.x);
                ffma2(acc2[i][3], ap, bB.y);
            }
        }
    }

    float bv[8];
    if (bias) {
        const float4 v0 = *reinterpret_cast<const float4*>(bias + tc * 8);
        const float4 v1 = *reinterpret_cast<const float4*>(bias + tc * 8 + 4);
        bv[0]=v0.x; bv[1]=v0.y; bv[2]=v0.z; bv[3]=v0.w;
        bv[4]=v1.x; bv[5]=v1.y; bv[6]=v1.z; bv[7]=v1.w;
    } else {
        #pragma unroll
        for (int j = 0; j < 8; ++j) bv[j] = 0.f;
    }

    #pragma unroll
    for (int i = 0; i < 8; ++i) {
        const int row = r0 + tr * 8 + i;
        if (row >= nrows) break;
        const size_t o = (size_t)row * NOUT + tc * 8;
        float v[8];
        #pragma unroll
        for (int p = 0; p < 4; ++p)
            unpack2(acc2[i][p], v[2 * p], v[2 * p + 1]);
        #pragma unroll
        for (int j = 0; j < 8; ++j) {
            float x = v[j] + bv[j];
            if (act) x = silu_f(x);
            v[j] = x;
        }
        if (mulv) {
            const float4 m0 = *reinterpret_cast<const float4*>(mulv + o);
            const float4 m1 = *reinterpret_cast<const float4*>(mulv + o + 4);
            v[0]*=m0.x; v[1]*=m0.y; v[2]*=m0.z; v[3]*=m0.w;
            v[4]*=m1.x; v[5]*=m1.y; v[6]*=m1.z; v[7]*=m1.w;
        }
        if (addv) {
            const float4 s0 = *reinterpret_cast<const float4*>(addv + o);
            const float4 s1 = *reinterpret_cast<const float4*>(addv + o + 4);
            v[0]+=s0.x; v[1]+=s0.y; v[2]+=s0.z; v[3]+=s0.w;
            v[4]+=s1.x; v[5]+=s1.y; v[6]+=s1.z; v[7]+=s1.w;
        }
        *reinterpret_cast<float4*>(out + o)     = make_float4(v[0], v[1], v[2], v[3]);
        *reinterpret_cast<float4*>(out + o + 4) = make_float4(v[4], v[5], v[6], v[7]);
        if (out2) {
            const float4 m0 = *reinterpret_cast<const float4*>(mul2 + o);
            const float4 m1 = *reinterpret_cast<const float4*>(mul2 + o + 4);
            *reinterpret_cast<float4*>(out2 + o)     = make_float4(v[0]*m0.x, v[1]*m0.y, v[2]*m0.z, v[3]*m0.w);
            *reinterpret_cast<float4*>(out2 + o + 4) = make_float4(v[4]*m1.x, v[5]*m1.y, v[6]*m1.z, v[7]*m1.w);
        }
    }
}

// ---------------- rbf basis helpers ----------------
__global__ void rb8_kernel(const float* __restrict__ rbf, const float* __restrict__ W1,
                           float* __restrict__ out, int n)
{
    const int e = blockIdx.x * blockDim.x + threadIdx.x;
    if (e >= n) return;
    float r[NRAD];
    #pragma unroll
    for (int i = 0; i < NRAD; ++i) r[i] = rbf[(size_t)e * NRAD + i];
    #pragma unroll
    for (int b = 0; b < BSZ; ++b) {
        float s = 0.f;
        #pragma unroll
        for (int i = 0; i < NRAD; ++i) s += r[i] * __ldg(&W1[i * BSZ + b]);
        out[(size_t)e * BSZ + b] = s;
    }
}

__global__ void rbfh_kernel(const float* __restrict__ rb8, const float* __restrict__ rbf,
                            const float* __restrict__ W_rbf2, const float* __restrict__ W_rbf,
                            float* __restrict__ rbfh, float* __restrict__ rbfh2, int n)
{
    __shared__ float w2[BSZ * HH];
    __shared__ float wr[NRAD * HH];
    const int j = threadIdx.x;
    #pragma unroll
    for (int b = 0; b < BSZ; ++b) w2[b * HH + j] = W_rbf2[b * HH + j];
    #pragma unroll
    for (int r = 0; r < NRAD; ++r) wr[r * HH + j] = W_rbf[r * HH + j];
    __syncthreads();

    const int row0 = blockIdx.x * 32;
    for (int rr = 0; rr < 32; ++rr) {
        const int row = row0 + rr;
        if (row >= n) return;
        const float4* rp = reinterpret_cast<const float4*>(rb8 + (size_t)row * BSZ);
        const float4 ra = __ldg(rp), rb = __ldg(rp + 1);
        float a1 = ra.x * w2[0 * HH + j] + ra.y * w2[1 * HH + j] +
                   ra.z * w2[2 * HH + j] + ra.w * w2[3 * HH + j] +
                   rb.x * w2[4 * HH + j] + rb.y * w2[5 * HH + j] +
                   rb.z * w2[6 * HH + j] + rb.w * w2[7 * HH + j];
        float a2 = 0.f;
        #pragma unroll
        for (int r = 0; r < NRAD; ++r) a2 += __ldg(&rbf[(size_t)row * NRAD + r]) * wr[r * HH + j];
        rbfh[(size_t)row * HH + j]  = a1;
        rbfh2[(size_t)row * HH + j] = a2;
    }
}

// ------- T-space proj: cp.async double-buffered tile streamer (R9) --------
template <int K, int PK>
__global__ void __launch_bounds__(256)
proj8cp(const float* __restrict__ X, const float* __restrict__ W1,
        float* __restrict__ out8, int nrows)
{
    constexpr int ROWS = 24;
    constexpr int TILE_F = ROWS * K;
    constexpr int CH = (TILE_F * 4) / 16;
    constexpr int ITERS = (K + 31) / 32;

    extern __shared__ float sm[];
    float* wcm  = sm;
    float* red  = sm + 8 * PK;
    float* buf0 = red + 8 * 32 * 33;
    float* buf1 = buf0 + TILE_F;

    const int tid = threadIdx.x;
    for (int x = tid; x < 8 * PK; x += 256) wcm[x] = 0.f;
    __syncthreads();
    for (int x = tid; x < K * 8; x += 256) {
        const int i = x / 8, b = x % 8;
        wcm[b * PK + i] = W1[x];
    }

    const int warp = tid >> 5, lane = tid & 31;
    const int G = gridDim.x;
    const int ntiles = (nrows + ROWS - 1) / ROWS;
    float* myred = red + warp * (32 * 33);

    const uint32_t b0u = smem_u32(buf0), b1u = smem_u32(buf1);

    int it = 0;
    if ((int)blockIdx.x < ntiles) {
        const char* gsrc = (const char*)X + (size_t)blockIdx.x * (ROWS * K * 4);
        for (int c = tid; c < CH; c += 256)
            asm volatile("cp.async.cg.shared.global [%0], [%1], 16;"
                         :: "r"(b0u + c * 16), "l"(gsrc + (size_t)c * 16));
    }
    asm volatile("cp.async.commit_group;" ::: "memory");

    for (int tt = blockIdx.x; tt < ntiles; tt += G, ++it) {
        float* cur = (it & 1) ? buf1 : buf0;
        const uint32_t nxtu = (it & 1) ? b0u : b1u;
        const int tnext = tt + G;
        if (tnext < ntiles) {
            const char* gsrc = (const char*)X + (size_t)tnext * (ROWS * K * 4);
            for (int c = tid; c < CH; c += 256)
                asm volatile("cp.async.cg.shared.global [%0], [%1], 16;"
                             :: "r"(nxtu + c * 16), "l"(gsrc + (size_t)c * 16));
            asm volatile("cp.async.commit_group;" ::: "memory");
            asm volatile("cp.async.wait_group 1;" ::: "memory");
        } else {
            asm volatile("cp.async.commit_group;" ::: "memory");
            asm volatile("cp.async.wait_group 0;" ::: "memory");
        }
        __syncthreads();

        const int r0 = tt * ROWS;
        float acc[3][BSZ] = {};
        const float* xb = cur + (3 * warp) * K;
        #pragma unroll
        for (int k = 0; k < ITERS; ++k) {
            const int ii = lane + k * 32;
            float x0 = 0.f, x1 = 0.f, x2 = 0.f;
            if (ii < K) { x0 = xb[ii]; x1 = xb[K + ii]; x2 = xb[2 * K + ii]; }
            #pragma unroll
            for (int b = 0; b < BSZ; ++b) {
                const float w = wcm[b * PK + ii];
                acc[0][b] += w * x0; acc[1][b] += w * x1; acc[2][b] += w * x2;
            }
        }
        #pragma unroll
        for (int rr = 0; rr < 3; ++rr)
            #pragma unroll
            for (int b = 0; b < BSZ; ++b)
                myred[lane * 33 + rr * BSZ + b] = acc[rr][b];
        __syncwarp();
        if (lane < 24) {
            float s = 0.f;
            #pragma unroll
            for (int l = 0; l < 32; ++l) s += myred[l * 33 + lane];
            const int row = r0 + 3 * warp + (lane >> 3);
            if (row < nrows)
                out8[(size_t)(r0 + 3 * warp) * BSZ + lane] = s;
        }
        __syncthreads();
    }
}

// ------- triplet gather/scale/scatter (EXACT R2/R3-era version) -----------
__global__ void triplet_kernel(const float* __restrict__ t8, const float* __restrict__ s8,
                               const float* __restrict__ W_t2, const float* __restrict__ W_sbf2,
                               const float* __restrict__ xdown,
                               const int* __restrict__ idx_kj, const int* __restrict__ idx_ji,
                               float* __restrict__ acc, int nt)
{
    __shared__ float wt2s[BSZ * IC];
    __shared__ float ws2s[BSZ * IC];
    const int tid = threadIdx.x;
    for (int i = tid; i < BSZ * IC; i += blockDim.x) { wt2s[i] = W_t2[i]; ws2s[i] = W_sbf2[i]; }
    __syncthreads();

    const int warp = tid >> 5, lane = tid & 31;
    const int total_warps = (blockDim.x * gridDim.x) >> 5;

    for (int tr = blockIdx.x * (blockDim.x >> 5) + warp; tr < nt; tr += total_warps) {
        const float4* tp = reinterpret_cast<const float4*>(t8 + (size_t)tr * BSZ);
        const float4 ta = __ldg(tp), tb = __ldg(tp + 1);
        const float4* sp = reinterpret_cast<const float4*>(s8 + (size_t)tr * BSZ);
        const float4 sa = __ldg(sp), sb = __ldg(sp + 1);
        const float tv[BSZ] = {ta.x, ta.y, ta.z, ta.w, tb.x, tb.y, tb.z, tb.w};
        const float sv[BSZ] = {sa.x, sa.y, sa.z, sa.w, sb.x, sb.y, sb.z, sb.w};
        const int kj = idx_kj[tr], ji = idx_ji[tr];
        const int c0 = lane, c1 = lane + 32;
        float t0 = 0.f, t1 = 0.f, s0 = 0.f, s1 = 0.f;
        #pragma unroll
        for (int b = 0; b < BSZ; ++b) {
            t0 += tv[b] * wt2s[b * IC + c0];
            t1 += tv[b] * wt2s[b * IC + c1];
            s0 += sv[b] * ws2s[b * IC + c0];
            s1 += sv[b] * ws2s[b * IC + c1];
        }
        const float g0 = xdown[(size_t)kj * IC + c0];
        const float g1 = xdown[(size_t)kj * IC + c1];
        atomicAdd(acc + (size_t)ji * IC + c0, g0 * t0 * s0);
        atomicAdd(acc + (size_t)ji * IC + c1, g1 * t1 * s1);
    }
}

__global__ void zero4_kernel(float4* __restrict__ p, int n4)
{
    const int i = blockIdx.x * blockDim.x + threadIdx.x;
    if (i < n4) p[i] = make_float4(0.f, 0.f, 0.f, 0.f);
}

// ---------------- streams/events (host objects; created pre-run) ----------
struct HxStreams {
    cudaStream_t s2;
    cudaEvent_t evF, evPs, evJ;
    HxStreams() {
        cudaStreamCreateWithFlags(&s2, cudaStreamNonBlocking);
        cudaEventCreateWithFlags(&evF, cudaEventDisableTiming);
        cudaEventCreateWithFlags(&evPs, cudaEventDisableTiming);
        cudaEventCreateWithFlags(&evJ, cudaEventDisableTiming);
    }
};
static HxStreams g_hx;

// -------- launch: proj chain (DRAM-bound) || gemm chain (fma-bound) -------
extern "C" void kernel_launch(void* const* d_in, const int* in_sizes, int n_in,
                              void* d_out, int out_size)
{
    const float* e1     = (const float*)d_in[0];
    const float* rbf    = (const float*)d_in[1];
    const float* sbf    = (const float*)d_in[2];
    const float* tt     = (const float*)d_in[3];
    const int*   idx_kj = (const int*)d_in[4];
    const int*   idx_ji = (const int*)d_in[5];
    const float* W_rbf1 = (const float*)d_in[6];
    const float* W_rbf2 = (const float*)d_in[7];
    const float* W_sbf1 = (const float*)d_in[8];
    const float* W_sbf2 = (const float*)d_in[9];
    const float* W_t1   = (const float*)d_in[10];
    const float* W_t2   = (const float*)d_in[11];
    const float* W_rbf  = (const float*)d_in[12];
    const float* W_kj   = (const float*)d_in[13];
    const float* b_kj   = (const float*)d_in[14];
    const float* W_ji   = (const float*)d_in[15];
    const float* b_ji   = (const float*)d_in[16];
    const float* W_down = (const float*)d_in[17];
    const float* W_up   = (const float*)d_in[18];
    const float* Wb1    = (const float*)d_in[19];
    const float* bb1    = (const float*)d_in[20];
    const float* Wb2    = (const float*)d_in[21];
    const float* bb2    = (const float*)d_in[22];
    const float* W_lin  = (const float*)d_in[23];
    const float* b_lin  = (const float*)d_in[24];
    const float* Wa1    = (const float*)d_in[25];
    const float* ba1    = (const float*)d_in[26];
    const float* Wa2    = (const float*)d_in[27];
    const float* ba2    = (const float*)d_in[28];

    const int E = in_sizes[0] / HH;
    const int T = in_sizes[4];

    float *xji, *rbfh, *rbfh2, *rb8, *xdown, *acc, *t8, *s8, *A, *B, *C;
    cudaGetSymbolAddress((void**)&xji,   g_xji);
    cudaGetSymbolAddress((void**)&rbfh,  g_rbfh);
    cudaGetSymbolAddress((void**)&rbfh2, g_rbfh2);
    cudaGetSymbolAddress((void**)&rb8,   g_rb8);
    cudaGetSymbolAddress((void**)&xdown, g_xdown);
    cudaGetSymbolAddress((void**)&acc,   g_acc);
    cudaGetSymbolAddress((void**)&t8,    g_t8);
    cudaGetSymbolAddress((void**)&s8,    g_s8);
    cudaGetSymbolAddress((void**)&A,     g_bufA);
    cudaGetSymbolAddress((void**)&B,     g_bufB);
    cudaGetSymbolAddress((void**)&C,     g_bufC);

    float* out_e1 = (float*)d_out;
    float* out_e2 = (float*)d_out + (size_t)E * HH;

    const int WS = HH * HH;

    const int sm_g128 = 64 * 132 * 4 + 64 * 128 * 4;   // 66560
    const int sm_gd   = 64 * 132 * 4 + 64 * 64 * 4;    // 50176
    const int sm_gu   = 64 * 132 * 4 + 64 * 128 * 4;   // 66560
    cudaFuncSetAttribute(gemm_rt<HH, HH>, cudaFuncAttributeMaxDynamicSharedMemorySize, sm_g128);
    cudaFuncSetAttribute(gemm_rt<HH, IC>, cudaFuncAttributeMaxDynamicSharedMemorySize, sm_gd);
    cudaFuncSetAttribute(gemm_rt<IC, HH>, cudaFuncAttributeMaxDynamicSharedMemorySize, sm_gu);

    const int sm_pt = (8 * 320 + 8 * 32 * 33 + 2 * 24 * TK) * 4;    // 100480
    const int sm_ps = (8 * 64 + 8 * 32 * 33 + 2 * 24 * SBFK) * 4;   // 43904
    cudaFuncSetAttribute(proj8cp<TK, 320>, cudaFuncAttributeMaxDynamicSharedMemorySize, sm_pt);
    cudaFuncSetAttribute(proj8cp<SBFK, 64>, cudaFuncAttributeMaxDynamicSharedMemorySize, sm_ps);

    const int gblocks = (E + 127) / 128;
    cudaStream_t s2 = g_hx.s2;

    // ---- fork: side stream runs DRAM-bound proj chain + zero, then ji ----
    cudaEventRecord(g_hx.evF, 0);
    cudaStreamWaitEvent(s2, g_hx.evF, 0);

    proj8cp<SBFK, 64><<<296, 256, sm_ps, s2>>>(sbf, W_sbf1, s8, T);                  // s2
    proj8cp<TK, 320><<<296, 256, sm_pt, s2>>>(tt, W_t1, t8, T);                      // s2
    zero4_kernel<<<(E * IC / 4 + 255) / 256, 256, 0, s2>>>((float4*)acc, E * IC / 4);// s2
    cudaEventRecord(g_hx.evPs, s2);
    // ji on s2: overlaps dn tail + triplet on main
    gemm_rt<HH, HH><<<gblocks, 256, sm_g128, s2>>>(e1, W_ji, b_ji, nullptr, nullptr, xji, nullptr, nullptr, E, 1);
    cudaEventRecord(g_hx.evJ, s2);

    // main chain (fma-bound): rbf basis -> kj -> dn
    rb8_kernel<<<(E + 255) / 256, 256>>>(rbf, W_rbf1, rb8, E);
    rbfh_kernel<<<(E + 31) / 32, HH>>>(rb8, rbf, W_rbf2, W_rbf, rbfh, rbfh2, E);
    gemm_rt<HH, HH><<<gblocks, 256, sm_g128>>>(e1, W_kj, b_kj, rbfh, nullptr, A, nullptr, nullptr, E, 1);
    gemm_rt<HH, IC><<<gblocks, 128, sm_gd>>>(A, W_down, nullptr, nullptr, nullptr, xdown, nullptr, nullptr, E, 1);

    // triplet needs t8/s8/acc (evPs) + xdown (main)
    cudaStreamWaitEvent(0, g_hx.evPs, 0);
    triplet_kernel<<<2368, 256>>>(t8, s8, W_t2, W_sbf2, xdown, idx_kj, idx_ji, acc, T);
    cudaStreamWaitEvent(0, g_hx.evJ, 0);
    // ---- join ----

    // A = silu(acc @ W_up) + x_ji
    gemm_rt<IC, HH><<<gblocks, 256, sm_gu>>>(acc, W_up, nullptr, nullptr, xji, A, nullptr, nullptr, E, 1);
    // residual before (1 layer)
    gemm_rt<HH, HH><<<gblocks, 256, sm_g128>>>(A, Wb1, bb1, nullptr, nullptr, B, nullptr, nullptr, E, 1);
    gemm_rt<HH, HH><<<gblocks, 256, sm_g128>>>(B, Wb2, bb2, nullptr, A, C, nullptr, nullptr, E, 1);
    // h = silu(C @ W_lin + b_lin) + e1
    gemm_rt<HH, HH><<<gblocks, 256, sm_g128>>>(C, W_lin, b_lin, nullptr, e1, A, nullptr, nullptr, E, 1);
    // residual after layer 0
    gemm_rt<HH, HH><<<gblocks, 256, sm_g128>>>(A, Wa1, ba1, nullptr, nullptr, B, nullptr, nullptr, E, 1);
    gemm_rt<HH, HH><<<gblocks, 256, sm_g128>>>(B, Wa2, ba2, nullptr, A, C, nullptr, nullptr, E, 1);
    // residual after layer 1 -> final outputs
    gemm_rt<HH, HH><<<gblocks, 256, sm_g128>>>(C, Wa1 + WS, ba1 + HH, nullptr, nullptr, B, nullptr, nullptr, E, 1);
    gemm_rt<HH, HH><<<gblocks, 256, sm_g128>>>(B, Wa2 + WS, ba2 + HH, nullptr, C, out_e1, rbfh2, out_e2, E, 1);
}